// round 1
// baseline (speedup 1.0000x reference)
#include <cuda_runtime.h>
#include <math.h>

// ---------------- scratch (static device globals; no runtime alloc) ----------------
__device__ float g_h1t[512 * 400 * 256];          // conv1 out, channel-last [b][s][co]  (210 MB)
__device__ float g_w2t[81 * 256 * 256];           // pc_w transposed [k][ci][co]          (21 MB)
__device__ float g_h2[512 * 9216];                // conv2 out flat [b][co*36+s]          (19 MB)
__device__ float g_u[512 * 9216];                 // squashed capsules [b][i][k]          (19 MB)
__device__ float g_xhat[(size_t)512 * 10 * 1152 * 16]; // votes [b][o][i][d]             (377 MB)
__device__ float g_blog[512 * 10 * 1152];         // routing logits [b][o][i]             (24 MB)
__device__ float g_v[512 * 10 * 16];              // routed caps per iter

// ---------------- conv1: [512,1,28,28] -> channel-last [512,400,256], ReLU ----------------
__global__ __launch_bounds__(256) void conv1_kernel(const float* __restrict__ x,
                                                    const float* __restrict__ w1,
                                                    const float* __restrict__ b1) {
    __shared__ float xs[784];
    int b  = blockIdx.x;
    int co = threadIdx.x;
    const float* xb = x + (size_t)b * 784;
    for (int idx = co; idx < 784; idx += 256) xs[idx] = xb[idx];
    __syncthreads();

    float bias = b1[co];
    const float* wco = w1 + co * 81;

    for (int oh = 0; oh < 20; oh++) {
        float acc[20];
#pragma unroll
        for (int ow = 0; ow < 20; ow++) acc[ow] = 0.f;

        for (int kh = 0; kh < 9; kh++) {
            float xr[28];
#pragma unroll
            for (int c = 0; c < 28; c++) xr[c] = xs[(oh + kh) * 28 + c];
#pragma unroll
            for (int kw = 0; kw < 9; kw++) {
                float w = __ldg(&wco[kh * 9 + kw]);
#pragma unroll
                for (int ow = 0; ow < 20; ow++) acc[ow] += w * xr[ow + kw];
            }
        }
        float* outp = g_h1t + (((size_t)b * 400) + oh * 20) * 256 + co;
#pragma unroll
        for (int ow = 0; ow < 20; ow++) {
            float v = acc[ow] + bias;
            outp[(size_t)ow * 256] = v > 0.f ? v : 0.f;
        }
    }
}

// ---------------- pc_w transpose: [co][ci][k] -> [k][ci][co] ----------------
__global__ void transpose_w2(const float* __restrict__ pcw) {
    int idx = blockIdx.x * 256 + threadIdx.x;   // idx = (k*256+ci)*256+co
    if (idx >= 81 * 256 * 256) return;
    int co = idx & 255;
    int ci = (idx >> 8) & 255;
    int k  = idx >> 16;
    g_w2t[idx] = pcw[((size_t)co * 256 + ci) * 81 + k];
}

// ---------------- primary-caps conv: 9x9 stride-2 -> g_h2 [b][co*36+s] ----------------
__global__ __launch_bounds__(256) void conv2_kernel(const float* __restrict__ pcb) {
    __shared__ float As[36 * 64];
    int b  = blockIdx.x;
    int co = threadIdx.x;

    float acc[36];
#pragma unroll
    for (int s = 0; s < 36; s++) acc[s] = 0.f;

    const float* h1b = g_h1t + (size_t)b * 400 * 256;

    for (int kh = 0; kh < 9; kh++) {
        for (int kw = 0; kw < 9; kw++) {
            int kk = kh * 9 + kw;
            for (int cb = 0; cb < 256; cb += 64) {
                __syncthreads();
                // stage [36 positions][64 channels], coalesced (channel-last input)
                for (int e = co; e < 36 * 64; e += 256) {
                    int s  = e >> 6;
                    int ci = e & 63;
                    int oh = s / 6, ow = s % 6;
                    As[e] = h1b[((2 * oh + kh) * 20 + (2 * ow + kw)) * 256 + cb + ci];
                }
                __syncthreads();

                const float* wp = g_w2t + (((size_t)kk * 256) + cb) * 256 + co;
#pragma unroll 4
                for (int ci = 0; ci < 64; ci++) {
                    float w = __ldg(&wp[(size_t)ci * 256]);
#pragma unroll
                    for (int s = 0; s < 36; s++) acc[s] += w * As[s * 64 + ci];
                }
            }
        }
    }
    float bias = pcb[co];
    float* outp = g_h2 + (size_t)b * 9216 + co * 36;
#pragma unroll
    for (int s = 0; s < 36; s++) outp[s] = acc[s] + bias;
}

// ---------------- squash over 8-dim capsules: g_h2 -> g_u ----------------
__global__ void squash_kernel() {
    int idx = blockIdx.x * 256 + threadIdx.x;   // capsule index: b*1152+i
    if (idx >= 512 * 1152) return;
    const float4* p = (const float4*)(g_h2 + (size_t)idx * 8);
    float4 a = p[0], c = p[1];
    float n2 = a.x * a.x + a.y * a.y + a.z * a.z + a.w * a.w +
               c.x * c.x + c.y * c.y + c.z * c.z + c.w * c.w;
    float n = sqrtf(n2);
    float scale = n2 / (1.f + n2) / (n + 1e-8f);
    float4* q = (float4*)(g_u + (size_t)idx * 8);
    a.x *= scale; a.y *= scale; a.z *= scale; a.w *= scale;
    c.x *= scale; c.y *= scale; c.z *= scale; c.w *= scale;
    q[0] = a; q[1] = c;
}

// ---------------- votes: x_hat[b,o,i,d] = sum_k caps_w[o,i,d,k] * u[b,i,k] ----------------
__global__ __launch_bounds__(256) void xhat_kernel(const float* __restrict__ cw) {
    int bo = blockIdx.x;          // b*10+o
    int b = bo / 10, o = bo % 10;
    for (int i = threadIdx.x; i < 1152; i += 256) {
        const float4* up = (const float4*)(g_u + ((size_t)b * 1152 + i) * 8);
        float4 ua = up[0], ub = up[1];
        const float* wp = cw + ((size_t)o * 1152 + i) * 128;
        float* xp = g_xhat + (((size_t)bo * 1152) + i) * 16;
#pragma unroll
        for (int d = 0; d < 16; d++) {
            const float4* w4 = (const float4*)(wp + d * 8);
            float4 wa = w4[0], wb = w4[1];
            xp[d] = wa.x * ua.x + wa.y * ua.y + wa.z * ua.z + wa.w * ua.w +
                    wb.x * ub.x + wb.y * ub.y + wb.z * ub.z + wb.w * ub.w;
        }
    }
}

// ---------------- routing A: c (uniform or softmax) -> weighted sum -> squash ----------------
// MODE 0: c = 0.1 (iter 0), write v.  MODE 1: softmax(b_logits), write v.
// MODE 2: softmax(b_logits), write capsule length to out.
template <int MODE>
__global__ __launch_bounds__(256) void routeA_kernel(float* __restrict__ out) {
    __shared__ float cs[1152];
    __shared__ float sred[256];
    __shared__ float sd[16];
    __shared__ float sscale;

    int bo = blockIdx.x;
    int b = bo / 10, o = bo % 10;
    int t = threadIdx.x;

    if (MODE > 0) {
        const float* blb = g_blog + (size_t)b * 10 * 1152;
        for (int i = t; i < 1152; i += 256) {
            float vals[10];
            float m = -1e30f;
#pragma unroll
            for (int oo = 0; oo < 10; oo++) {
                vals[oo] = blb[(size_t)oo * 1152 + i];
                m = fmaxf(m, vals[oo]);
            }
            float sum = 0.f;
#pragma unroll
            for (int oo = 0; oo < 10; oo++) sum += expf(vals[oo] - m);
            cs[i] = expf(vals[o] - m) / sum;
        }
    } else {
        for (int i = t; i < 1152; i += 256) cs[i] = 0.1f;
    }
    __syncthreads();

    int d = t & 15, g = t >> 4;
    float acc = 0.f;
    const float* xb = g_xhat + (size_t)bo * 1152 * 16;
    for (int i = g; i < 1152; i += 16)
        acc += cs[i] * xb[(size_t)i * 16 + d];
    sred[t] = acc;
    __syncthreads();

    if (t < 16) {
        float s = 0.f;
#pragma unroll
        for (int gg = 0; gg < 16; gg++) s += sred[gg * 16 + t];
        sd[t] = s;
    }
    __syncthreads();

    if (t == 0) {
        float n2 = 0.f;
#pragma unroll
        for (int dd = 0; dd < 16; dd++) n2 += sd[dd] * sd[dd];
        float n = sqrtf(n2);
        float scale = n2 / (1.f + n2) / (n + 1e-8f);
        sscale = scale;
        if (MODE == 2) out[bo] = scale * n;   // length of squashed capsule
    }
    __syncthreads();

    if (MODE < 2 && t < 16) g_v[(size_t)bo * 16 + t] = sscale * sd[t];
}

// ---------------- routing B: b_logits update with v . x_hat ----------------
// FIRST=1: write (iter 0, logits start at 0). FIRST=0: accumulate.
template <int FIRST>
__global__ __launch_bounds__(256) void routeB_kernel() {
    __shared__ float vs[16];
    int bo = blockIdx.x;
    int t = threadIdx.x;
    if (t < 16) vs[t] = g_v[(size_t)bo * 16 + t];
    __syncthreads();

    const float* xb = g_xhat + (size_t)bo * 1152 * 16;
    float* blp = g_blog + (size_t)bo * 1152;
    for (int i = t; i < 1152; i += 256) {
        const float4* x4 = (const float4*)(xb + (size_t)i * 16);
        float4 a = x4[0], b4 = x4[1], c4 = x4[2], e4 = x4[3];
        float dotv = a.x * vs[0]  + a.y * vs[1]  + a.z * vs[2]  + a.w * vs[3]
                   + b4.x * vs[4] + b4.y * vs[5] + b4.z * vs[6] + b4.w * vs[7]
                   + c4.x * vs[8] + c4.y * vs[9] + c4.z * vs[10]+ c4.w * vs[11]
                   + e4.x * vs[12]+ e4.y * vs[13]+ e4.z * vs[14]+ e4.w * vs[15];
        blp[i] = FIRST ? dotv : (blp[i] + dotv);
    }
}

// ---------------- launch ----------------
extern "C" void kernel_launch(void* const* d_in, const int* in_sizes, int n_in,
                              void* d_out, int out_size) {
    const float* x   = (const float*)d_in[0];
    const float* w1  = (const float*)d_in[1];
    const float* b1  = (const float*)d_in[2];
    const float* w2  = (const float*)d_in[3];
    const float* b2  = (const float*)d_in[4];
    const float* cw  = (const float*)d_in[5];
    float* out = (float*)d_out;

    conv1_kernel<<<512, 256>>>(x, w1, b1);
    transpose_w2<<<(81 * 256 * 256 + 255) / 256, 256>>>(w2);
    conv2_kernel<<<512, 256>>>(b2);
    squash_kernel<<<(512 * 1152 + 255) / 256, 256>>>();
    xhat_kernel<<<5120, 256>>>(cw);

    routeA_kernel<0><<<5120, 256>>>(nullptr);   // iter 0: uniform c
    routeB_kernel<1><<<5120, 256>>>();          // logits = v.xhat
    routeA_kernel<1><<<5120, 256>>>(nullptr);   // iter 1
    routeB_kernel<0><<<5120, 256>>>();          // logits += v.xhat
    routeA_kernel<2><<<5120, 256>>>(out);       // iter 2: lengths
}

// round 2
// speedup vs baseline: 1.2686x; 1.2686x over previous
#include <cuda_runtime.h>
#include <math.h>

// ---------------- scratch (static device globals; no runtime alloc) ----------------
__device__ float g_h1t[512 * 400 * 256];          // conv1 out, channel-last [b][s][co]  (210 MB)
__device__ float g_w2t[81 * 256 * 256];           // pc_w transposed [k][ci][co]          (21 MB)
__device__ float g_h2[512 * 9216];                // conv2 out flat [b][co*36+s]          (19 MB)
__device__ float g_u[512 * 9216];                 // squashed capsules [b][i][k]          (19 MB)
__device__ float g_xhat[(size_t)512 * 10 * 1152 * 16]; // votes [b][o][i][d]             (377 MB)
__device__ float g_blog[512 * 10 * 1152];         // routing logits [b][o][i]             (24 MB)
__device__ float g_v[512 * 10 * 16];              // routed caps per iter

// packed fp32x2 FMA (sm_103a): acc = a*b + acc, two fp32 lanes per instruction
__device__ __forceinline__ void ffma2(unsigned long long& acc,
                                      unsigned long long a,
                                      unsigned long long b) {
    asm("fma.rn.f32x2 %0, %1, %2, %0;" : "+l"(acc) : "l"(a), "l"(b));
}

// ---------------- conv1: [512,1,28,28] -> channel-last [512,400,256], ReLU ----------------
__global__ __launch_bounds__(256) void conv1_kernel(const float* __restrict__ x,
                                                    const float* __restrict__ w1,
                                                    const float* __restrict__ b1) {
    __shared__ float xs[784];
    int b  = blockIdx.x;
    int co = threadIdx.x;
    const float* xb = x + (size_t)b * 784;
    for (int idx = co; idx < 784; idx += 256) xs[idx] = xb[idx];
    __syncthreads();

    float bias = b1[co];
    const float* wco = w1 + co * 81;

    for (int oh = 0; oh < 20; oh++) {
        float acc[20];
#pragma unroll
        for (int ow = 0; ow < 20; ow++) acc[ow] = 0.f;

        for (int kh = 0; kh < 9; kh++) {
            float xr[28];
#pragma unroll
            for (int c = 0; c < 28; c++) xr[c] = xs[(oh + kh) * 28 + c];
#pragma unroll
            for (int kw = 0; kw < 9; kw++) {
                float w = __ldg(&wco[kh * 9 + kw]);
#pragma unroll
                for (int ow = 0; ow < 20; ow++) acc[ow] += w * xr[ow + kw];
            }
        }
        float* outp = g_h1t + (((size_t)b * 400) + oh * 20) * 256 + co;
#pragma unroll
        for (int ow = 0; ow < 20; ow++) {
            float v = acc[ow] + bias;
            outp[(size_t)ow * 256] = v > 0.f ? v : 0.f;
        }
    }
}

// ---------------- pc_w transpose: [co][ci][k] -> [k][ci][co] ----------------
__global__ void transpose_w2(const float* __restrict__ pcw) {
    int idx = blockIdx.x * 256 + threadIdx.x;   // idx = (k*256+ci)*256+co
    if (idx >= 81 * 256 * 256) return;
    int co = idx & 255;
    int ci = (idx >> 8) & 255;
    int k  = idx >> 16;
    g_w2t[idx] = pcw[((size_t)co * 256 + ci) * 81 + k];
}

// ---------------- primary-caps conv: 9x9 stride-2 -> g_h2 [b][co*36+s] ----------------
// f32x2 packed-FMA version: 18 packed accumulators over s-pairs, input staged [ci][s].
__global__ __launch_bounds__(256, 4) void conv2_kernel(const float* __restrict__ pcb) {
    __shared__ float As[64 * 36];   // [ci][s], row = 144B (16B-aligned for LDS.128)
    int b  = blockIdx.x;
    int co = threadIdx.x;

    unsigned long long acc2[18];
#pragma unroll
    for (int p = 0; p < 18; p++) acc2[p] = 0ull;

    const float* h1b = g_h1t + (size_t)b * 400 * 256;

    for (int kh = 0; kh < 9; kh++) {
        for (int kw = 0; kw < 9; kw++) {
            int kk = kh * 9 + kw;
            for (int cb = 0; cb < 256; cb += 64) {
                __syncthreads();
                // stage [64 ci][36 s]; global reads coalesced over ci (channel-last input)
                for (int e = co; e < 36 * 64; e += 256) {
                    int s  = e >> 6;
                    int ci = e & 63;
                    int oh = s / 6, ow = s % 6;
                    As[ci * 36 + s] = h1b[((2 * oh + kh) * 20 + (2 * ow + kw)) * 256 + cb + ci];
                }
                __syncthreads();

                const float* wp = g_w2t + (((size_t)kk * 256) + cb) * 256 + co;
                for (int ci = 0; ci < 64; ci++) {
                    float w = __ldg(&wp[(size_t)ci * 256]);
                    unsigned long long w2;
                    asm("mov.b64 %0, {%1, %1};" : "=l"(w2) : "f"(w));
                    const ulonglong2* arow = (const ulonglong2*)(As + ci * 36);
#pragma unroll
                    for (int p = 0; p < 9; p++) {
                        ulonglong2 a4 = arow[p];            // LDS.128: s-pairs (4 floats)
                        ffma2(acc2[2 * p],     a4.x, w2);
                        ffma2(acc2[2 * p + 1], a4.y, w2);
                    }
                }
            }
        }
    }
    float bias = pcb[co];
    float* outp = g_h2 + (size_t)b * 9216 + co * 36;
#pragma unroll
    for (int p = 0; p < 18; p++) {
        float lo, hi;
        asm("mov.b64 {%0, %1}, %2;" : "=f"(lo), "=f"(hi) : "l"(acc2[p]));
        outp[2 * p]     = lo + bias;
        outp[2 * p + 1] = hi + bias;
    }
}

// ---------------- squash over 8-dim capsules: g_h2 -> g_u ----------------
__global__ void squash_kernel() {
    int idx = blockIdx.x * 256 + threadIdx.x;   // capsule index: b*1152+i
    if (idx >= 512 * 1152) return;
    const float4* p = (const float4*)(g_h2 + (size_t)idx * 8);
    float4 a = p[0], c = p[1];
    float n2 = a.x * a.x + a.y * a.y + a.z * a.z + a.w * a.w +
               c.x * c.x + c.y * c.y + c.z * c.z + c.w * c.w;
    float n = sqrtf(n2);
    float scale = n2 / (1.f + n2) / (n + 1e-8f);
    float4* q = (float4*)(g_u + (size_t)idx * 8);
    a.x *= scale; a.y *= scale; a.z *= scale; a.w *= scale;
    c.x *= scale; c.y *= scale; c.z *= scale; c.w *= scale;
    q[0] = a; q[1] = c;
}

// ---------------- votes: x_hat[b,o,i,d] = sum_k caps_w[o,i,d,k] * u[b,i,k] ----------------
__global__ __launch_bounds__(256) void xhat_kernel(const float* __restrict__ cw) {
    int bo = blockIdx.x;          // b*10+o
    int b = bo / 10, o = bo % 10;
    for (int i = threadIdx.x; i < 1152; i += 256) {
        const float4* up = (const float4*)(g_u + ((size_t)b * 1152 + i) * 8);
        float4 ua = up[0], ub = up[1];
        const float* wp = cw + ((size_t)o * 1152 + i) * 128;
        float4* xp = (float4*)(g_xhat + (((size_t)bo * 1152) + i) * 16);
        float r[16];
#pragma unroll
        for (int d = 0; d < 16; d++) {
            const float4* w4 = (const float4*)(wp + d * 8);
            float4 wa = w4[0], wb = w4[1];
            r[d] = wa.x * ua.x + wa.y * ua.y + wa.z * ua.z + wa.w * ua.w +
                   wb.x * ub.x + wb.y * ub.y + wb.z * ub.z + wb.w * ub.w;
        }
#pragma unroll
        for (int q = 0; q < 4; q++)
            xp[q] = make_float4(r[4 * q], r[4 * q + 1], r[4 * q + 2], r[4 * q + 3]);
    }
}

// ---------------- routing A: c (uniform or softmax) -> weighted sum -> squash ----------------
// MODE 0: c = 0.1 (iter 0), write v.  MODE 1: softmax(b_logits), write v.
// MODE 2: softmax(b_logits), write capsule length to out.
template <int MODE>
__global__ __launch_bounds__(256) void routeA_kernel(float* __restrict__ out) {
    __shared__ float cs[1152];
    __shared__ float sred[256];
    __shared__ float sd[16];
    __shared__ float sscale;

    int bo = blockIdx.x;
    int b = bo / 10, o = bo % 10;
    int t = threadIdx.x;

    if (MODE > 0) {
        const float* blb = g_blog + (size_t)b * 10 * 1152;
        for (int i = t; i < 1152; i += 256) {
            float vals[10];
            float m = -1e30f;
#pragma unroll
            for (int oo = 0; oo < 10; oo++) {
                vals[oo] = blb[(size_t)oo * 1152 + i];
                m = fmaxf(m, vals[oo]);
            }
            float sum = 0.f;
#pragma unroll
            for (int oo = 0; oo < 10; oo++) sum += expf(vals[oo] - m);
            cs[i] = expf(vals[o] - m) / sum;
        }
    } else {
        for (int i = t; i < 1152; i += 256) cs[i] = 0.1f;
    }
    __syncthreads();

    int d = t & 15, g = t >> 4;
    float acc = 0.f;
    const float* xb = g_xhat + (size_t)bo * 1152 * 16;
    for (int i = g; i < 1152; i += 16)
        acc += cs[i] * xb[(size_t)i * 16 + d];
    sred[t] = acc;
    __syncthreads();

    if (t < 16) {
        float s = 0.f;
#pragma unroll
        for (int gg = 0; gg < 16; gg++) s += sred[gg * 16 + t];
        sd[t] = s;
    }
    __syncthreads();

    if (t == 0) {
        float n2 = 0.f;
#pragma unroll
        for (int dd = 0; dd < 16; dd++) n2 += sd[dd] * sd[dd];
        float n = sqrtf(n2);
        float scale = n2 / (1.f + n2) / (n + 1e-8f);
        sscale = scale;
        if (MODE == 2) out[bo] = scale * n;   // length of squashed capsule
    }
    __syncthreads();

    if (MODE < 2 && t < 16) g_v[(size_t)bo * 16 + t] = sscale * sd[t];
}

// ---------------- routing B: b_logits update with v . x_hat ----------------
// FIRST=1: write (iter 0, logits start at 0). FIRST=0: accumulate.
template <int FIRST>
__global__ __launch_bounds__(256) void routeB_kernel() {
    __shared__ float vs[16];
    int bo = blockIdx.x;
    int t = threadIdx.x;
    if (t < 16) vs[t] = g_v[(size_t)bo * 16 + t];
    __syncthreads();

    const float* xb = g_xhat + (size_t)bo * 1152 * 16;
    float* blp = g_blog + (size_t)bo * 1152;
    for (int i = t; i < 1152; i += 256) {
        const float4* x4 = (const float4*)(xb + (size_t)i * 16);
        float4 a = x4[0], b4 = x4[1], c4 = x4[2], e4 = x4[3];
        float dotv = a.x * vs[0]  + a.y * vs[1]  + a.z * vs[2]  + a.w * vs[3]
                   + b4.x * vs[4] + b4.y * vs[5] + b4.z * vs[6] + b4.w * vs[7]
                   + c4.x * vs[8] + c4.y * vs[9] + c4.z * vs[10]+ c4.w * vs[11]
                   + e4.x * vs[12]+ e4.y * vs[13]+ e4.z * vs[14]+ e4.w * vs[15];
        blp[i] = FIRST ? dotv : (blp[i] + dotv);
    }
}

// ---------------- launch ----------------
extern "C" void kernel_launch(void* const* d_in, const int* in_sizes, int n_in,
                              void* d_out, int out_size) {
    const float* x   = (const float*)d_in[0];
    const float* w1  = (const float*)d_in[1];
    const float* b1  = (const float*)d_in[2];
    const float* w2  = (const float*)d_in[3];
    const float* b2  = (const float*)d_in[4];
    const float* cw  = (const float*)d_in[5];
    float* out = (float*)d_out;

    conv1_kernel<<<512, 256>>>(x, w1, b1);
    transpose_w2<<<(81 * 256 * 256 + 255) / 256, 256>>>(w2);
    conv2_kernel<<<512, 256>>>(b2);
    squash_kernel<<<(512 * 1152 + 255) / 256, 256>>>();
    xhat_kernel<<<5120, 256>>>(cw);

    routeA_kernel<0><<<5120, 256>>>(nullptr);   // iter 0: uniform c
    routeB_kernel<1><<<5120, 256>>>();          // logits = v.xhat
    routeA_kernel<1><<<5120, 256>>>(nullptr);   // iter 1
    routeB_kernel<0><<<5120, 256>>>();          // logits += v.xhat
    routeA_kernel<2><<<5120, 256>>>(out);       // iter 2: lengths
}

// round 3
// speedup vs baseline: 1.2990x; 1.0239x over previous
#include <cuda_runtime.h>
#include <math.h>

// ---------------- scratch (static device globals; no runtime alloc) ----------------
__device__ float g_h1t[512 * 400 * 256];          // conv1 out, channel-last [b][s][co]
__device__ float g_w2t[81 * 256 * 256];           // pc_w transposed [k][ci][co]
__device__ float g_h2[512 * 9216];                // conv2 out flat [b][co*36+s]
__device__ float g_u[512 * 9216];                 // squashed capsules [b][i][k]
__device__ float g_xhat[(size_t)512 * 10 * 1152 * 16]; // votes [b][o][i][d]
__device__ float g_blog0[512 * 10 * 1152];        // routing logits ping
__device__ float g_blog1[512 * 10 * 1152];        // routing logits pong

// packed fp32x2 FMA (sm_103a)
__device__ __forceinline__ void ffma2(unsigned long long& acc,
                                      unsigned long long a,
                                      unsigned long long b) {
    asm("fma.rn.f32x2 %0, %1, %2, %0;" : "+l"(acc) : "l"(a), "l"(b));
}

// ---------------- conv1: [512,1,28,28] -> channel-last [512,400,256], ReLU ----------------
__global__ __launch_bounds__(256) void conv1_kernel(const float* __restrict__ x,
                                                    const float* __restrict__ w1,
                                                    const float* __restrict__ b1) {
    __shared__ float xs[784];
    int b  = blockIdx.x;
    int co = threadIdx.x;
    const float* xb = x + (size_t)b * 784;
    for (int idx = co; idx < 784; idx += 256) xs[idx] = xb[idx];
    __syncthreads();

    float bias = b1[co];
    const float* wco = w1 + co * 81;

    for (int oh = 0; oh < 20; oh++) {
        float acc[20];
#pragma unroll
        for (int ow = 0; ow < 20; ow++) acc[ow] = 0.f;

        for (int kh = 0; kh < 9; kh++) {
            float xr[28];
#pragma unroll
            for (int c = 0; c < 28; c++) xr[c] = xs[(oh + kh) * 28 + c];
#pragma unroll
            for (int kw = 0; kw < 9; kw++) {
                float w = __ldg(&wco[kh * 9 + kw]);
#pragma unroll
                for (int ow = 0; ow < 20; ow++) acc[ow] += w * xr[ow + kw];
            }
        }
        float* outp = g_h1t + (((size_t)b * 400) + oh * 20) * 256 + co;
#pragma unroll
        for (int ow = 0; ow < 20; ow++) {
            float v = acc[ow] + bias;
            outp[(size_t)ow * 256] = v > 0.f ? v : 0.f;
        }
    }
}

// ---------------- pc_w transpose (coalesced, smem tile): [co][ci][k] -> [k][ci][co] ----------------
// grid: (ci, co_tile of 32). Reads 81-contiguous runs, writes 128B-coalesced.
__global__ __launch_bounds__(256) void transpose_w2(const float* __restrict__ pcw) {
    __shared__ float t[32 * 81];
    int ci = blockIdx.x;
    int cot = blockIdx.y;           // co tile: co = cot*32 + col
    int tid = threadIdx.x;

    for (int e = tid; e < 32 * 81; e += 256) {
        int col = e / 81, k = e % 81;
        t[e] = pcw[(((size_t)(cot * 32 + col)) * 256 + ci) * 81 + k];
    }
    __syncthreads();
    for (int e = tid; e < 32 * 81; e += 256) {
        int k = e / 32, col = e % 32;
        g_w2t[((size_t)k * 256 + ci) * 256 + cot * 32 + col] = t[col * 81 + k];
    }
}

// ---------------- primary-caps conv: 9x9 stride-2 -> g_h2 [b][co*36+s] ----------------
// cb-outer so live g_h1t footprint per block is one 102KB slab (L2-resident across SMs).
__global__ __launch_bounds__(256, 4) void conv2_kernel(const float* __restrict__ pcb) {
    __shared__ float As[64 * 36];   // [ci][s]
    int b  = blockIdx.x;
    int co = threadIdx.x;

    unsigned long long acc2[18];
#pragma unroll
    for (int p = 0; p < 18; p++) acc2[p] = 0ull;

    const float* h1b = g_h1t + (size_t)b * 400 * 256;

    for (int cb = 0; cb < 256; cb += 64) {
        for (int kh = 0; kh < 9; kh++) {
            for (int kw = 0; kw < 9; kw++) {
                int kk = kh * 9 + kw;
                __syncthreads();
                for (int e = co; e < 36 * 64; e += 256) {
                    int s  = e >> 6;
                    int ci = e & 63;
                    int oh = s / 6, ow = s % 6;
                    As[ci * 36 + s] = h1b[((2 * oh + kh) * 20 + (2 * ow + kw)) * 256 + cb + ci];
                }
                __syncthreads();

                const float* wp = g_w2t + (((size_t)kk * 256) + cb) * 256 + co;
                float w_next = __ldg(&wp[0]);
                for (int ci = 0; ci < 64; ci++) {
                    float w = w_next;
                    if (ci < 63) w_next = __ldg(&wp[(size_t)(ci + 1) * 256]);
                    unsigned long long w2;
                    asm("mov.b64 %0, {%1, %1};" : "=l"(w2) : "f"(w));
                    const ulonglong2* arow = (const ulonglong2*)(As + ci * 36);
#pragma unroll
                    for (int p = 0; p < 9; p++) {
                        ulonglong2 a4 = arow[p];
                        ffma2(acc2[2 * p],     a4.x, w2);
                        ffma2(acc2[2 * p + 1], a4.y, w2);
                    }
                }
            }
        }
    }
    float bias = pcb[co];
    float* outp = g_h2 + (size_t)b * 9216 + co * 36;
#pragma unroll
    for (int p = 0; p < 18; p++) {
        float lo, hi;
        asm("mov.b64 {%0, %1}, %2;" : "=f"(lo), "=f"(hi) : "l"(acc2[p]));
        outp[2 * p]     = lo + bias;
        outp[2 * p + 1] = hi + bias;
    }
}

// ---------------- squash over 8-dim capsules: g_h2 -> g_u ----------------
__global__ void squash_kernel() {
    int idx = blockIdx.x * 256 + threadIdx.x;
    if (idx >= 512 * 1152) return;
    const float4* p = (const float4*)(g_h2 + (size_t)idx * 8);
    float4 a = p[0], c = p[1];
    float n2 = a.x * a.x + a.y * a.y + a.z * a.z + a.w * a.w +
               c.x * c.x + c.y * c.y + c.z * c.z + c.w * c.w;
    float n = sqrtf(n2);
    float scale = n2 / (1.f + n2) / (n + 1e-8f);
    float4* q = (float4*)(g_u + (size_t)idx * 8);
    a.x *= scale; a.y *= scale; a.z *= scale; a.w *= scale;
    c.x *= scale; c.y *= scale; c.z *= scale; c.w *= scale;
    q[0] = a; q[1] = c;
}

// ---------------- votes: x_hat[b,o,i,d] = sum_k caps_w[o,i,d,k] * u[b,i,k] ----------------
__global__ __launch_bounds__(256) void xhat_kernel(const float* __restrict__ cw) {
    int bo = blockIdx.x;
    int b = bo / 10, o = bo % 10;
    for (int i = threadIdx.x; i < 1152; i += 256) {
        const float4* up = (const float4*)(g_u + ((size_t)b * 1152 + i) * 8);
        float4 ua = up[0], ub = up[1];
        const float* wp = cw + ((size_t)o * 1152 + i) * 128;
        float4* xp = (float4*)(g_xhat + (((size_t)bo * 1152) + i) * 16);
        float r[16];
#pragma unroll
        for (int d = 0; d < 16; d++) {
            const float4* w4 = (const float4*)(wp + d * 8);
            float4 wa = w4[0], wb = w4[1];
            r[d] = wa.x * ua.x + wa.y * ua.y + wa.z * ua.z + wa.w * ua.w +
                   wb.x * ub.x + wb.y * ub.y + wb.z * ub.z + wb.w * ub.w;
        }
#pragma unroll
        for (int q = 0; q < 4; q++)
            xp[q] = make_float4(r[4 * q], r[4 * q + 1], r[4 * q + 2], r[4 * q + 3]);
    }
}

// ---------------- fused routing A+B: c -> v (squash) -> logit update ----------------
// MODE 0: c = 0.1, blog_out = v.xhat.   MODE 1: c = softmax(blog_in), blog_out = blog_in + v.xhat.
// x_hat tile held in padded smem (stride 17 to kill bank conflicts).
template <int MODE>
__global__ __launch_bounds__(256) void routeAB_kernel(const float* __restrict__ blin_g,
                                                      float* __restrict__ blout_g) {
    extern __shared__ float sm[];
    float* xs = sm;                 // [1152][17]
    float* cs = sm + 1152 * 17;    // [1152]
    __shared__ float sred[256];
    __shared__ float sd[16];
    __shared__ float sscale;

    int bo = blockIdx.x;
    int b = bo / 10, o = bo % 10;
    int t = threadIdx.x;

    // load x_hat tile into padded smem
    const float4* xg = (const float4*)(g_xhat + (size_t)bo * 1152 * 16);
    for (int j = t; j < 1152 * 4; j += 256) {
        float4 v4 = xg[j];
        int i = j >> 2, q = j & 3;
        float* dst = xs + i * 17 + q * 4;
        dst[0] = v4.x; dst[1] = v4.y; dst[2] = v4.z; dst[3] = v4.w;
    }

    if (MODE == 1) {
        const float* blb = g_blog0 + (size_t)b * 10 * 1152;
        for (int i = t; i < 1152; i += 256) {
            float vals[10];
            float m = -1e30f;
#pragma unroll
            for (int oo = 0; oo < 10; oo++) {
                vals[oo] = blb[(size_t)oo * 1152 + i];
                m = fmaxf(m, vals[oo]);
            }
            float sum = 0.f;
#pragma unroll
            for (int oo = 0; oo < 10; oo++) sum += expf(vals[oo] - m);
            cs[i] = expf(vals[o] - m) / sum;
        }
    } else {
        for (int i = t; i < 1152; i += 256) cs[i] = 0.1f;
    }
    __syncthreads();

    // s_d = sum_i c_i * xhat[i][d]
    int d = t & 15, g = t >> 4;
    float acc = 0.f;
    for (int i = g; i < 1152; i += 16)
        acc += cs[i] * xs[i * 17 + d];
    sred[t] = acc;
    __syncthreads();

    if (t < 16) {
        float s = 0.f;
#pragma unroll
        for (int gg = 0; gg < 16; gg++) s += sred[gg * 16 + t];
        sd[t] = s;
    }
    __syncthreads();

    if (t == 0) {
        float n2 = 0.f;
#pragma unroll
        for (int dd = 0; dd < 16; dd++) n2 += sd[dd] * sd[dd];
        float n = sqrtf(n2);
        sscale = n2 / (1.f + n2) / (n + 1e-8f);
    }
    __syncthreads();

    // blog_out[i] = blog_in[i] + sum_d v_d * xhat[i][d],  v = sscale * sd
    float scale = sscale;
    const float* blin = blin_g + (size_t)bo * 1152;
    float* blout = blout_g + (size_t)bo * 1152;
    for (int i = t; i < 1152; i += 256) {
        float dot = 0.f;
        const float* xr = xs + i * 17;
#pragma unroll
        for (int dd = 0; dd < 16; dd++) dot += sd[dd] * xr[dd];
        dot *= scale;
        blout[i] = (MODE == 1) ? (blin[i] + dot) : dot;
    }
}

// ---------------- final routing pass: softmax(blog1) -> capsule lengths ----------------
__global__ __launch_bounds__(256) void routeFinal_kernel(float* __restrict__ out) {
    __shared__ float cs[1152];
    __shared__ float sred[256];
    __shared__ float sd[16];

    int bo = blockIdx.x;
    int b = bo / 10, o = bo % 10;
    int t = threadIdx.x;

    const float* blb = g_blog1 + (size_t)b * 10 * 1152;
    for (int i = t; i < 1152; i += 256) {
        float vals[10];
        float m = -1e30f;
#pragma unroll
        for (int oo = 0; oo < 10; oo++) {
            vals[oo] = blb[(size_t)oo * 1152 + i];
            m = fmaxf(m, vals[oo]);
        }
        float sum = 0.f;
#pragma unroll
        for (int oo = 0; oo < 10; oo++) sum += expf(vals[oo] - m);
        cs[i] = expf(vals[o] - m) / sum;
    }
    __syncthreads();

    int d = t & 15, g = t >> 4;
    float acc = 0.f;
    const float* xb = g_xhat + (size_t)bo * 1152 * 16;
    for (int i = g; i < 1152; i += 16)
        acc += cs[i] * xb[(size_t)i * 16 + d];
    sred[t] = acc;
    __syncthreads();

    if (t < 16) {
        float s = 0.f;
#pragma unroll
        for (int gg = 0; gg < 16; gg++) s += sred[gg * 16 + t];
        sd[t] = s;
    }
    __syncthreads();

    if (t == 0) {
        float n2 = 0.f;
#pragma unroll
        for (int dd = 0; dd < 16; dd++) n2 += sd[dd] * sd[dd];
        float n = sqrtf(n2);
        float scale = n2 / (1.f + n2) / (n + 1e-8f);
        out[bo] = scale * n;
    }
}

// ---------------- launch ----------------
extern "C" void kernel_launch(void* const* d_in, const int* in_sizes, int n_in,
                              void* d_out, int out_size) {
    const float* x   = (const float*)d_in[0];
    const float* w1  = (const float*)d_in[1];
    const float* b1  = (const float*)d_in[2];
    const float* w2  = (const float*)d_in[3];
    const float* b2  = (const float*)d_in[4];
    const float* cw  = (const float*)d_in[5];
    float* out = (float*)d_out;

    const int ROUTE_SMEM = (1152 * 17 + 1152) * 4;   // 82944 B
    cudaFuncSetAttribute(routeAB_kernel<0>, cudaFuncAttributeMaxDynamicSharedMemorySize, ROUTE_SMEM);
    cudaFuncSetAttribute(routeAB_kernel<1>, cudaFuncAttributeMaxDynamicSharedMemorySize, ROUTE_SMEM);

    // resolve device-global addresses for ping-pong logits
    float *blog0, *blog1;
    cudaGetSymbolAddress((void**)&blog0, g_blog0);
    cudaGetSymbolAddress((void**)&blog1, g_blog1);

    conv1_kernel<<<512, 256>>>(x, w1, b1);
    transpose_w2<<<dim3(256, 8), 256>>>(w2);
    conv2_kernel<<<512, 256>>>(b2);
    squash_kernel<<<(512 * 1152 + 255) / 256, 256>>>();
    xhat_kernel<<<5120, 256>>>(cw);

    routeAB_kernel<0><<<5120, 256, ROUTE_SMEM>>>(blog0, blog0);  // iter 0: uniform c -> blog0
    routeAB_kernel<1><<<5120, 256, ROUTE_SMEM>>>(blog0, blog1);  // iter 1: softmax(blog0) -> blog1
    routeFinal_kernel<<<5120, 256>>>(out);                       // iter 2: lengths from blog1
}

// round 5
// speedup vs baseline: 3.2016x; 2.4647x over previous
#include <cuda_runtime.h>
#include <cuda_bf16.h>
#include <math.h>
#include <stdint.h>

// ---------------- scratch (static device globals; no runtime alloc) ----------------
__device__ __nv_bfloat16 g_h1_hi[(size_t)512 * 400 * 256];   // conv1 out hi, [b][pos][ci]
__device__ __nv_bfloat16 g_h1_lo[(size_t)512 * 400 * 256];   // conv1 out lo
__device__ __nv_bfloat16 g_w2_hi[81 * 256 * 256];            // pc_w hi, [kk][co][ci]
__device__ __nv_bfloat16 g_w2_lo[81 * 256 * 256];            // pc_w lo
__device__ float g_h2[512 * 9216];                           // conv2 out [b][co*36+s]
__device__ float g_u[512 * 9216];                            // squashed capsules [b][i][k]
__device__ float g_xhat[(size_t)512 * 10 * 1152 * 16];       // votes [b][o][i][d]
__device__ float g_blog0[512 * 10 * 1152];                   // routing logits ping
__device__ float g_blog1[512 * 10 * 1152];                   // routing logits pong

// ---------------- PTX helpers (sm_80-era: compile for plain sm_103 target) ----------------
__device__ __forceinline__ uint32_t smem_u32(const void* p) {
    uint32_t a;
    asm("{ .reg .u64 t; cvta.to.shared.u64 t, %1; cvt.u32.u64 %0, t; }" : "=r"(a) : "l"(p));
    return a;
}
__device__ __forceinline__ void ldm_x4(uint32_t* r, uint32_t addr) {
    asm volatile("ldmatrix.sync.aligned.m8n8.x4.shared.b16 {%0,%1,%2,%3}, [%4];"
                 : "=r"(r[0]), "=r"(r[1]), "=r"(r[2]), "=r"(r[3]) : "r"(addr));
}
__device__ __forceinline__ void mma_bf16(float* c, const uint32_t* a, const uint32_t* b) {
    asm volatile("mma.sync.aligned.m16n8k16.row.col.f32.bf16.bf16.f32 "
                 "{%0,%1,%2,%3}, {%4,%5,%6,%7}, {%8,%9}, {%0,%1,%2,%3};"
                 : "+f"(c[0]), "+f"(c[1]), "+f"(c[2]), "+f"(c[3])
                 : "r"(a[0]), "r"(a[1]), "r"(a[2]), "r"(a[3]), "r"(b[0]), "r"(b[1]));
}

// ---------------- conv1: [512,1,28,28] -> channel-last bf16 hi/lo [512,400,256], ReLU ----------------
__global__ __launch_bounds__(256) void conv1_kernel(const float* __restrict__ x,
                                                    const float* __restrict__ w1,
                                                    const float* __restrict__ b1) {
    __shared__ float xs[784];
    int b  = blockIdx.x;
    int co = threadIdx.x;
    const float* xb = x + (size_t)b * 784;
    for (int idx = co; idx < 784; idx += 256) xs[idx] = xb[idx];
    __syncthreads();

    float bias = b1[co];
    const float* wco = w1 + co * 81;

    for (int oh = 0; oh < 20; oh++) {
        float acc[20];
#pragma unroll
        for (int ow = 0; ow < 20; ow++) acc[ow] = 0.f;

        for (int kh = 0; kh < 9; kh++) {
            float xr[28];
#pragma unroll
            for (int c = 0; c < 28; c++) xr[c] = xs[(oh + kh) * 28 + c];
#pragma unroll
            for (int kw = 0; kw < 9; kw++) {
                float w = __ldg(&wco[kh * 9 + kw]);
#pragma unroll
                for (int ow = 0; ow < 20; ow++) acc[ow] += w * xr[ow + kw];
            }
        }
        size_t base = (((size_t)b * 400) + oh * 20) * 256 + co;
#pragma unroll
        for (int ow = 0; ow < 20; ow++) {
            float v = acc[ow] + bias;
            v = v > 0.f ? v : 0.f;
            __nv_bfloat16 h = __float2bfloat16(v);
            __nv_bfloat16 l = __float2bfloat16(v - __bfloat162float(h));
            g_h1_hi[base + (size_t)ow * 256] = h;
            g_h1_lo[base + (size_t)ow * 256] = l;
        }
    }
}

// ---------------- pc_w convert: [co][ci][k] fp32 -> [kk][co][ci] bf16 hi/lo ----------------
__global__ __launch_bounds__(256) void convert_w2(const float* __restrict__ pcw) {
    int idx = blockIdx.x * 256 + threadIdx.x;   // co*256+ci
    if (idx >= 65536) return;
    int co = idx >> 8, ci = idx & 255;
    const float* src = pcw + (size_t)idx * 81;
    for (int k = 0; k < 81; k++) {
        float v = src[k];
        __nv_bfloat16 h = __float2bfloat16(v);
        __nv_bfloat16 l = __float2bfloat16(v - __bfloat162float(h));
        size_t o = ((size_t)k * 256 + co) * 256 + ci;
        g_w2_hi[o] = h;
        g_w2_lo[o] = l;
    }
}

// ---------------- conv2 via HMMA implicit GEMM ----------------
// C[128co x 128pos] per CTA; 8 warps of 32x64; bf16 hi/lo 3-term split.
// smem rows padded to 72 bf16 (144B) -> conflict-free ldmatrix.
#define LDK 72
__global__ __launch_bounds__(256, 2) void conv2_mma(const float* __restrict__ pcb) {
    extern __shared__ char smem[];
    const int AHI = 0, ALO = 18432, BHI = 36864, BLO = 55296;

    uint32_t sb = smem_u32(smem);
    int tid = threadIdx.x;
    int wid = tid >> 5;
    int lane = tid & 31;
    int mtile = blockIdx.x;      // 0..1  (co block of 128)
    int ntile = blockIdx.y;      // 0..143 (pos block of 128)

    int wm = wid & 3;            // 4 warps in m: 32 rows each
    int wn = wid >> 2;           // 2 warps in n: 64 cols each

    float acc[2][8][4];
#pragma unroll
    for (int mt = 0; mt < 2; mt++)
#pragma unroll
        for (int nt = 0; nt < 8; nt++)
#pragma unroll
            for (int j = 0; j < 4; j++) acc[mt][nt][j] = 0.f;

    // ldmatrix lane-address components (byte offsets into a [row][LDK] bf16 matrix)
    int rowA = lane & 15;
    int kgA  = (lane >> 4) << 3;
    int rowB = ((lane >> 4) << 3) + (lane & 7);
    int kgB  = ((lane >> 3) & 1) << 3;

    for (int cb = 0; cb < 256; cb += 64) {
        for (int kk = 0; kk < 81; kk++) {
            int kh = kk / 9, kw = kk % 9;
            __syncthreads();
            // stage A: 128 co rows x 64 ci (hi + lo)
            for (int e = tid; e < 1024; e += 256) {
                int row = e >> 3, seg = e & 7;
                size_t src = (((size_t)kk * 256) + mtile * 128 + row) * 256 + cb + seg * 8;
                uint32_t dst = (uint32_t)(row * LDK + seg * 8) * 2;
                *(uint4*)(smem + AHI + dst) = *(const uint4*)((const char*)g_w2_hi + src * 2);
                *(uint4*)(smem + ALO + dst) = *(const uint4*)((const char*)g_w2_lo + src * 2);
            }
            // stage B: 128 pos rows x 64 ci (hi + lo)
            for (int e = tid; e < 1024; e += 256) {
                int row = e >> 3, seg = e & 7;
                int p = ntile * 128 + row;
                int b = p / 36;
                int s = p - b * 36;
                int oh = s / 6, ow = s - oh * 6;
                size_t src = ((size_t)b * 400 + (2 * oh + kh) * 20 + (2 * ow + kw)) * 256 + cb + seg * 8;
                uint32_t dst = (uint32_t)(row * LDK + seg * 8) * 2;
                *(uint4*)(smem + BHI + dst) = *(const uint4*)((const char*)g_h1_hi + src * 2);
                *(uint4*)(smem + BLO + dst) = *(const uint4*)((const char*)g_h1_lo + src * 2);
            }
            __syncthreads();

#pragma unroll
            for (int ks = 0; ks < 4; ks++) {
                int k0 = ks * 16;
                uint32_t ahi[2][4], alo[2][4];
#pragma unroll
                for (int mt = 0; mt < 2; mt++) {
                    uint32_t arow = (uint32_t)((wm * 32 + mt * 16 + rowA) * LDK + k0 + kgA) * 2;
                    ldm_x4(ahi[mt], sb + AHI + arow);
                    ldm_x4(alo[mt], sb + ALO + arow);
                }
                // two n-halves of 32 cols to bound live registers
#pragma unroll
                for (int nh = 0; nh < 2; nh++) {
                    uint32_t bhi[4][2], blo[4][2];
#pragma unroll
                    for (int nq = 0; nq < 2; nq++) {
                        uint32_t brow = (uint32_t)((wn * 64 + nh * 32 + nq * 16 + rowB) * LDK + k0 + kgB) * 2;
                        uint32_t t4[4];
                        ldm_x4(t4, sb + BHI + brow);
                        bhi[2 * nq][0] = t4[0]; bhi[2 * nq][1] = t4[1];
                        bhi[2 * nq + 1][0] = t4[2]; bhi[2 * nq + 1][1] = t4[3];
                        ldm_x4(t4, sb + BLO + brow);
                        blo[2 * nq][0] = t4[0]; blo[2 * nq][1] = t4[1];
                        blo[2 * nq + 1][0] = t4[2]; blo[2 * nq + 1][1] = t4[3];
                    }
#pragma unroll
                    for (int mt = 0; mt < 2; mt++)
#pragma unroll
                        for (int nq = 0; nq < 4; nq++) {
                            int nt = nh * 4 + nq;
                            mma_bf16(acc[mt][nt], ahi[mt], bhi[nq]);
                            mma_bf16(acc[mt][nt], ahi[mt], blo[nq]);
                            mma_bf16(acc[mt][nt], alo[mt], bhi[nq]);
                        }
                }
            }
        }
    }

    // epilogue: add bias, scatter to g_h2[b*9216 + co*36 + s]
    int r0 = lane >> 2, cp = lane & 3;
#pragma unroll
    for (int mt = 0; mt < 2; mt++) {
#pragma unroll
        for (int half = 0; half < 2; half++) {
            int m = wm * 32 + mt * 16 + r0 + half * 8;
            int co = mtile * 128 + m;
            float bias = pcb[co];
#pragma unroll
            for (int nt = 0; nt < 8; nt++) {
#pragma unroll
                for (int e = 0; e < 2; e++) {
                    int p = ntile * 128 + wn * 64 + nt * 8 + 2 * cp + e;
                    int b = p / 36;
                    int s = p - b * 36;
                    g_h2[(size_t)b * 9216 + co * 36 + s] = acc[mt][nt][half * 2 + e] + bias;
                }
            }
        }
    }
}

// ---------------- squash over 8-dim capsules: g_h2 -> g_u ----------------
__global__ void squash_kernel() {
    int idx = blockIdx.x * 256 + threadIdx.x;
    if (idx >= 512 * 1152) return;
    const float4* p = (const float4*)(g_h2 + (size_t)idx * 8);
    float4 a = p[0], c = p[1];
    float n2 = a.x * a.x + a.y * a.y + a.z * a.z + a.w * a.w +
               c.x * c.x + c.y * c.y + c.z * c.z + c.w * c.w;
    float n = sqrtf(n2);
    float scale = n2 / (1.f + n2) / (n + 1e-8f);
    float4* q = (float4*)(g_u + (size_t)idx * 8);
    a.x *= scale; a.y *= scale; a.z *= scale; a.w *= scale;
    c.x *= scale; c.y *= scale; c.z *= scale; c.w *= scale;
    q[0] = a; q[1] = c;
}

// ---------------- votes: x_hat[b,o,i,d] = sum_k caps_w[o,i,d,k] * u[b,i,k] ----------------
__global__ __launch_bounds__(256) void xhat_kernel(const float* __restrict__ cw) {
    int bo = blockIdx.x;
    int b = bo / 10, o = bo % 10;
    for (int i = threadIdx.x; i < 1152; i += 256) {
        const float4* up = (const float4*)(g_u + ((size_t)b * 1152 + i) * 8);
        float4 ua = up[0], ub = up[1];
        const float* wp = cw + ((size_t)o * 1152 + i) * 128;
        float4* xp = (float4*)(g_xhat + (((size_t)bo * 1152) + i) * 16);
        float r[16];
#pragma unroll
        for (int d = 0; d < 16; d++) {
            const float4* w4 = (const float4*)(wp + d * 8);
            float4 wa = w4[0], wb = w4[1];
            r[d] = wa.x * ua.x + wa.y * ua.y + wa.z * ua.z + wa.w * ua.w +
                   wb.x * ub.x + wb.y * ub.y + wb.z * ub.z + wb.w * ub.w;
        }
#pragma unroll
        for (int q = 0; q < 4; q++)
            xp[q] = make_float4(r[4 * q], r[4 * q + 1], r[4 * q + 2], r[4 * q + 3]);
    }
}

// ---------------- fused routing A+B ----------------
template <int MODE>
__global__ __launch_bounds__(256) void routeAB_kernel(const float* __restrict__ blin_g,
                                                      float* __restrict__ blout_g) {
    extern __shared__ float sm[];
    float* xs = sm;                 // [1152][17]
    float* cs = sm + 1152 * 17;     // [1152]
    __shared__ float sred[256];
    __shared__ float sd[16];
    __shared__ float sscale;

    int bo = blockIdx.x;
    int b = bo / 10, o = bo % 10;
    int t = threadIdx.x;

    const float4* xg = (const float4*)(g_xhat + (size_t)bo * 1152 * 16);
    for (int j = t; j < 1152 * 4; j += 256) {
        float4 v4 = xg[j];
        int i = j >> 2, q = j & 3;
        float* dst = xs + i * 17 + q * 4;
        dst[0] = v4.x; dst[1] = v4.y; dst[2] = v4.z; dst[3] = v4.w;
    }

    if (MODE == 1) {
        const float* blb = g_blog0 + (size_t)b * 10 * 1152;
        for (int i = t; i < 1152; i += 256) {
            float vals[10];
            float m = -1e30f;
#pragma unroll
            for (int oo = 0; oo < 10; oo++) {
                vals[oo] = blb[(size_t)oo * 1152 + i];
                m = fmaxf(m, vals[oo]);
            }
            float sum = 0.f;
#pragma unroll
            for (int oo = 0; oo < 10; oo++) sum += expf(vals[oo] - m);
            cs[i] = expf(vals[o] - m) / sum;
        }
    } else {
        for (int i = t; i < 1152; i += 256) cs[i] = 0.1f;
    }
    __syncthreads();

    int d = t & 15, g = t >> 4;
    float acc = 0.f;
    for (int i = g; i < 1152; i += 16)
        acc += cs[i] * xs[i * 17 + d];
    sred[t] = acc;
    __syncthreads();

    if (t < 16) {
        float s = 0.f;
#pragma unroll
        for (int gg = 0; gg < 16; gg++) s += sred[gg * 16 + t];
        sd[t] = s;
    }
    __syncthreads();

    if (t == 0) {
        float n2 = 0.f;
#pragma unroll
        for (int dd = 0; dd < 16; dd++) n2 += sd[dd] * sd[dd];
        float n = sqrtf(n2);
        sscale = n2 / (1.f + n2) / (n + 1e-8f);
    }
    __syncthreads();

    float scale = sscale;
    const float* blin = blin_g + (size_t)bo * 1152;
    float* blout = blout_g + (size_t)bo * 1152;
    for (int i = t; i < 1152; i += 256) {
        float dot = 0.f;
        const float* xr = xs + i * 17;
#pragma unroll
        for (int dd = 0; dd < 16; dd++) dot += sd[dd] * xr[dd];
        dot *= scale;
        blout[i] = (MODE == 1) ? (blin[i] + dot) : dot;
    }
}

// ---------------- final routing pass: softmax(blog1) -> capsule lengths ----------------
__global__ __launch_bounds__(256) void routeFinal_kernel(float* __restrict__ out) {
    __shared__ float cs[1152];
    __shared__ float sred[256];
    __shared__ float sd[16];

    int bo = blockIdx.x;
    int b = bo / 10, o = bo % 10;
    int t = threadIdx.x;

    const float* blb = g_blog1 + (size_t)b * 10 * 1152;
    for (int i = t; i < 1152; i += 256) {
        float vals[10];
        float m = -1e30f;
#pragma unroll
        for (int oo = 0; oo < 10; oo++) {
            vals[oo] = blb[(size_t)oo * 1152 + i];
            m = fmaxf(m, vals[oo]);
        }
        float sum = 0.f;
#pragma unroll
        for (int oo = 0; oo < 10; oo++) sum += expf(vals[oo] - m);
        cs[i] = expf(vals[o] - m) / sum;
    }
    __syncthreads();

    int d = t & 15, g = t >> 4;
    float acc = 0.f;
    const float* xb = g_xhat + (size_t)bo * 1152 * 16;
    for (int i = g; i < 1152; i += 16)
        acc += cs[i] * xb[(size_t)i * 16 + d];
    sred[t] = acc;
    __syncthreads();

    if (t < 16) {
        float s = 0.f;
#pragma unroll
        for (int gg = 0; gg < 16; gg++) s += sred[gg * 16 + t];
        sd[t] = s;
    }
    __syncthreads();

    if (t == 0) {
        float n2 = 0.f;
#pragma unroll
        for (int dd = 0; dd < 16; dd++) n2 += sd[dd] * sd[dd];
        float n = sqrtf(n2);
        float scale = n2 / (1.f + n2) / (n + 1e-8f);
        out[bo] = scale * n;
    }
}

// ---------------- launch ----------------
extern "C" void kernel_launch(void* const* d_in, const int* in_sizes, int n_in,
                              void* d_out, int out_size) {
    const float* x   = (const float*)d_in[0];
    const float* w1  = (const float*)d_in[1];
    const float* b1  = (const float*)d_in[2];
    const float* w2  = (const float*)d_in[3];
    const float* b2  = (const float*)d_in[4];
    const float* cw  = (const float*)d_in[5];
    float* out = (float*)d_out;

    const int CONV2_SMEM = 73728;                      // 4 x 18432B tiles
    const int ROUTE_SMEM = (1152 * 17 + 1152) * 4;     // 82944 B
    cudaFuncSetAttribute(conv2_mma, cudaFuncAttributeMaxDynamicSharedMemorySize, CONV2_SMEM);
    cudaFuncSetAttribute(routeAB_kernel<0>, cudaFuncAttributeMaxDynamicSharedMemorySize, ROUTE_SMEM);
    cudaFuncSetAttribute(routeAB_kernel<1>, cudaFuncAttributeMaxDynamicSharedMemorySize, ROUTE_SMEM);

    float *blog0, *blog1;
    cudaGetSymbolAddress((void**)&blog0, g_blog0);
    cudaGetSymbolAddress((void**)&blog1, g_blog1);

    conv1_kernel<<<512, 256>>>(x, w1, b1);
    convert_w2<<<256, 256>>>(w2);
    conv2_mma<<<dim3(2, 144), 256, CONV2_SMEM>>>(b2);
    squash_kernel<<<(512 * 1152 + 255) / 256, 256>>>();
    xhat_kernel<<<5120, 256>>>(cw);

    routeAB_kernel<0><<<5120, 256, ROUTE_SMEM>>>(blog0, blog0);
    routeAB_kernel<1><<<5120, 256, ROUTE_SMEM>>>(blog0, blog1);
    routeFinal_kernel<<<5120, 256>>>(out);
}

// round 6
// speedup vs baseline: 3.5029x; 1.0941x over previous
#include <cuda_runtime.h>
#include <cuda_bf16.h>
#include <math.h>
#include <stdint.h>

// ---------------- scratch (static device globals; no runtime alloc) ----------------
__device__ __nv_bfloat16 g_h1_hi[(size_t)512 * 400 * 256];   // conv1 out hi, [b][pos][ci]
__device__ __nv_bfloat16 g_h1_lo[(size_t)512 * 400 * 256];   // conv1 out lo
__device__ __nv_bfloat16 g_w2_hi[81 * 256 * 256];            // pc_w hi, [kk][co][ci]
__device__ __nv_bfloat16 g_w2_lo[81 * 256 * 256];            // pc_w lo
__device__ float g_h2[512 * 9216];                           // conv2 out [b][co*36+s]
__device__ float g_u[512 * 9216];                            // squashed capsules [b][i][k]
__device__ float g_xhat[(size_t)512 * 10 * 1152 * 16];       // votes [b][o][i][d]
__device__ float g_blog0[512 * 10 * 1152];                   // routing logits ping
__device__ float g_blog1[512 * 10 * 1152];                   // routing logits pong

// ---------------- PTX helpers (sm_80-era; compile on plain sm_103 target) ----------------
__device__ __forceinline__ uint32_t smem_u32(const void* p) {
    uint32_t a;
    asm("{ .reg .u64 t; cvta.to.shared.u64 t, %1; cvt.u32.u64 %0, t; }" : "=r"(a) : "l"(p));
    return a;
}
__device__ __forceinline__ void ldm_x4(uint32_t* r, uint32_t addr) {
    asm volatile("ldmatrix.sync.aligned.m8n8.x4.shared.b16 {%0,%1,%2,%3}, [%4];"
                 : "=r"(r[0]), "=r"(r[1]), "=r"(r[2]), "=r"(r[3]) : "r"(addr));
}
__device__ __forceinline__ void mma_bf16(float* c, const uint32_t* a, const uint32_t* b) {
    asm volatile("mma.sync.aligned.m16n8k16.row.col.f32.bf16.bf16.f32 "
                 "{%0,%1,%2,%3}, {%4,%5,%6,%7}, {%8,%9}, {%0,%1,%2,%3};"
                 : "+f"(c[0]), "+f"(c[1]), "+f"(c[2]), "+f"(c[3])
                 : "r"(a[0]), "r"(a[1]), "r"(a[2]), "r"(a[3]), "r"(b[0]), "r"(b[1]));
}
__device__ __forceinline__ void cp16(uint32_t dst, const void* src) {
    asm volatile("cp.async.cg.shared.global [%0], [%1], 16;" :: "r"(dst), "l"(src));
}
__device__ __forceinline__ void cp_commit() { asm volatile("cp.async.commit_group;" ::: "memory"); }
__device__ __forceinline__ void cp_wait0()  { asm volatile("cp.async.wait_group 0;" ::: "memory"); }

// ---------------- conv1: [512,1,28,28] -> channel-last bf16 hi/lo [512,400,256], ReLU ----------------
__global__ __launch_bounds__(256) void conv1_kernel(const float* __restrict__ x,
                                                    const float* __restrict__ w1,
                                                    const float* __restrict__ b1) {
    __shared__ float xs[784];
    int b  = blockIdx.x;
    int co = threadIdx.x;
    const float* xb = x + (size_t)b * 784;
    for (int idx = co; idx < 784; idx += 256) xs[idx] = xb[idx];
    __syncthreads();

    float bias = b1[co];
    const float* wco = w1 + co * 81;

    for (int oh = 0; oh < 20; oh++) {
        float acc[20];
#pragma unroll
        for (int ow = 0; ow < 20; ow++) acc[ow] = 0.f;

        for (int kh = 0; kh < 9; kh++) {
            float xr[28];
#pragma unroll
            for (int c = 0; c < 28; c++) xr[c] = xs[(oh + kh) * 28 + c];
#pragma unroll
            for (int kw = 0; kw < 9; kw++) {
                float w = __ldg(&wco[kh * 9 + kw]);
#pragma unroll
                for (int ow = 0; ow < 20; ow++) acc[ow] += w * xr[ow + kw];
            }
        }
        size_t base = (((size_t)b * 400) + oh * 20) * 256 + co;
#pragma unroll
        for (int ow = 0; ow < 20; ow++) {
            float v = acc[ow] + bias;
            v = v > 0.f ? v : 0.f;
            __nv_bfloat16 h = __float2bfloat16(v);
            __nv_bfloat16 l = __float2bfloat16(v - __bfloat162float(h));
            g_h1_hi[base + (size_t)ow * 256] = h;
            g_h1_lo[base + (size_t)ow * 256] = l;
        }
    }
}

// ---------------- pc_w convert (coalesced): [co][ci][k] fp32 -> [kk][co][ci] bf16 hi/lo ----------------
// one block per co: contiguous 20736-float read into smem, then per-k coalesced stores over ci.
__global__ __launch_bounds__(256) void convert_w2(const float* __restrict__ pcw) {
    extern __shared__ float ws[];    // [ci][81]
    int co = blockIdx.x;
    int t = threadIdx.x;
    const float* src = pcw + (size_t)co * 256 * 81;
    for (int idx = t; idx < 256 * 81; idx += 256) ws[idx] = src[idx];
    __syncthreads();
    int ci = t;
    for (int k = 0; k < 81; k++) {
        float v = ws[ci * 81 + k];
        __nv_bfloat16 h = __float2bfloat16(v);
        __nv_bfloat16 l = __float2bfloat16(v - __bfloat162float(h));
        size_t o = ((size_t)k * 256 + co) * 256 + ci;
        g_w2_hi[o] = h;
        g_w2_lo[o] = l;
    }
}

// ---------------- conv2 via HMMA implicit GEMM, cp.async double-buffered ----------------
// C[128co x 256pos] per CTA; 8 warps (4m x 2n), warp tile 32m x 128n; bf16 hi/lo 3-term.
// smem per buffer: AHI 18432 + ALO 18432 + BHI 36864 + BLO 36864 = 110592; x2 buffers.
#define LDK 72
#define BUFSZ 110592
#define AHI 0
#define ALO 18432
#define BHI 36864
#define BLO 73728
#define NITER 324
__global__ __launch_bounds__(256, 1) void conv2_mma(const float* __restrict__ pcb) {
    extern __shared__ char smem[];
    uint32_t sb = smem_u32(smem);
    int tid = threadIdx.x;
    int wid = tid >> 5;
    int lane = tid & 31;
    int mtile = blockIdx.x;      // 0..1   (co block of 128)
    int ntile = blockIdx.y;      // 0..71  (pos block of 256)

    int wm = wid & 3;            // 4 warps in m: 32 rows each
    int wn = wid >> 2;           // 2 warps in n: 128 cols each

    // ---- per-thread staging precompute ----
    int seg = tid & 7;           // 16B segment within a 64-ci row
    int rbase = tid >> 3;        // 0..31
    uint32_t adst[4];
    uint32_t aoff[4];
#pragma unroll
    for (int j = 0; j < 4; j++) {
        int row = rbase + j * 32;                       // 0..127
        adst[j] = (uint32_t)(row * LDK + seg * 8) * 2;
        aoff[j] = (uint32_t)((mtile * 128 + row) * 256 + seg * 8);
    }
    uint32_t bdst[8];
    size_t gb[8];
#pragma unroll
    for (int j = 0; j < 8; j++) {
        int row = rbase + j * 32;                       // 0..255
        bdst[j] = (uint32_t)(row * LDK + seg * 8) * 2;
        int p = ntile * 256 + row;
        int b = p / 36;
        int s = p - b * 36;
        int oh = s / 6, ow = s - oh * 6;
        gb[j] = ((size_t)b * 400 + oh * 40 + ow * 2) * 256 + seg * 8;
    }

    float acc[2][16][4];
#pragma unroll
    for (int mt = 0; mt < 2; mt++)
#pragma unroll
        for (int nt = 0; nt < 16; nt++)
#pragma unroll
            for (int j = 0; j < 4; j++) acc[mt][nt][j] = 0.f;

    int rowA = lane & 15;
    int kgA  = (lane >> 4) << 3;
    int rowB = ((lane >> 4) << 3) + (lane & 7);
    int kgB  = ((lane >> 3) & 1) << 3;

    // ---- staging macro ----
#define STAGE(IT, BSEL) do {                                                        \
        int _it = (IT);                                                             \
        int _cb = (_it / 81) << 6;                                                  \
        int _kk = _it - (_it / 81) * 81;                                            \
        int _kh = _kk / 9, _kw = _kk - _kh * 9;                                     \
        uint32_t _bu = sb + (BSEL) * BUFSZ;                                         \
        size_t _abase = ((size_t)_kk * 256) * 256 + _cb;                            \
        size_t _boff = (size_t)(_kh * 20 + _kw) * 256 + _cb;                        \
        _Pragma("unroll")                                                           \
        for (int j = 0; j < 4; j++) {                                               \
            size_t _s = _abase + aoff[j];                                           \
            cp16(_bu + AHI + adst[j], (const char*)g_w2_hi + _s * 2);               \
            cp16(_bu + ALO + adst[j], (const char*)g_w2_lo + _s * 2);               \
        }                                                                           \
        _Pragma("unroll")                                                           \
        for (int j = 0; j < 8; j++) {                                               \
            size_t _s = gb[j] + _boff;                                              \
            cp16(_bu + BHI + bdst[j], (const char*)g_h1_hi + _s * 2);               \
            cp16(_bu + BLO + bdst[j], (const char*)g_h1_lo + _s * 2);               \
        }                                                                           \
    } while (0)

    STAGE(0, 0);
    cp_commit();
    cp_wait0();
    __syncthreads();

    for (int it = 0; it < NITER; it++) {
        if (it + 1 < NITER) { STAGE(it + 1, (it + 1) & 1); cp_commit(); }

        uint32_t bu = sb + (it & 1) * BUFSZ;
#pragma unroll
        for (int ks = 0; ks < 4; ks++) {
            int k0 = ks * 16;
            uint32_t ahi[2][4], alo[2][4];
#pragma unroll
            for (int mt = 0; mt < 2; mt++) {
                uint32_t arow = (uint32_t)((wm * 32 + mt * 16 + rowA) * LDK + k0 + kgA) * 2;
                ldm_x4(ahi[mt], bu + AHI + arow);
                ldm_x4(alo[mt], bu + ALO + arow);
            }
#pragma unroll
            for (int nh = 0; nh < 4; nh++) {        // 4 chunks of 32 cols
                uint32_t bhi[4][2], blo[4][2];
#pragma unroll
                for (int nq = 0; nq < 2; nq++) {
                    uint32_t brow = (uint32_t)((wn * 128 + nh * 32 + nq * 16 + rowB) * LDK + k0 + kgB) * 2;
                    uint32_t t4[4];
                    ldm_x4(t4, bu + BHI + brow);
                    bhi[2 * nq][0] = t4[0]; bhi[2 * nq][1] = t4[1];
                    bhi[2 * nq + 1][0] = t4[2]; bhi[2 * nq + 1][1] = t4[3];
                    ldm_x4(t4, bu + BLO + brow);
                    blo[2 * nq][0] = t4[0]; blo[2 * nq][1] = t4[1];
                    blo[2 * nq + 1][0] = t4[2]; blo[2 * nq + 1][1] = t4[3];
                }
#pragma unroll
                for (int mt = 0; mt < 2; mt++)
#pragma unroll
                    for (int nq = 0; nq < 4; nq++) {
                        int nt = nh * 4 + nq;
                        mma_bf16(acc[mt][nt], ahi[mt], bhi[nq]);
                        mma_bf16(acc[mt][nt], ahi[mt], blo[nq]);
                        mma_bf16(acc[mt][nt], alo[mt], bhi[nq]);
                    }
            }
        }
        if (it + 1 < NITER) cp_wait0();
        __syncthreads();
    }

    // epilogue: add bias, scatter to g_h2[b*9216 + co*36 + s]
    int r0 = lane >> 2, cp = lane & 3;
#pragma unroll
    for (int mt = 0; mt < 2; mt++) {
#pragma unroll
        for (int half = 0; half < 2; half++) {
            int m = wm * 32 + mt * 16 + r0 + half * 8;
            int co = mtile * 128 + m;
            float bias = pcb[co];
#pragma unroll
            for (int nt = 0; nt < 16; nt++) {
#pragma unroll
                for (int e = 0; e < 2; e++) {
                    int p = ntile * 256 + wn * 128 + nt * 8 + 2 * cp + e;
                    int b = p / 36;
                    int s = p - b * 36;
                    g_h2[(size_t)b * 9216 + co * 36 + s] = acc[mt][nt][half * 2 + e] + bias;
                }
            }
        }
    }
}

// ---------------- squash over 8-dim capsules: g_h2 -> g_u ----------------
__global__ void squash_kernel() {
    int idx = blockIdx.x * 256 + threadIdx.x;
    if (idx >= 512 * 1152) return;
    const float4* p = (const float4*)(g_h2 + (size_t)idx * 8);
    float4 a = p[0], c = p[1];
    float n2 = a.x * a.x + a.y * a.y + a.z * a.z + a.w * a.w +
               c.x * c.x + c.y * c.y + c.z * c.z + c.w * c.w;
    float n = sqrtf(n2);
    float scale = n2 / (1.f + n2) / (n + 1e-8f);
    float4* q = (float4*)(g_u + (size_t)idx * 8);
    a.x *= scale; a.y *= scale; a.z *= scale; a.w *= scale;
    c.x *= scale; c.y *= scale; c.z *= scale; c.w *= scale;
    q[0] = a; q[1] = c;
}

// ---------------- votes: x_hat[b,o,i,d] = sum_k caps_w[o,i,d,k] * u[b,i,k] ----------------
__global__ __launch_bounds__(256) void xhat_kernel(const float* __restrict__ cw) {
    int bo = blockIdx.x;
    int b = bo / 10, o = bo % 10;
    for (int i = threadIdx.x; i < 1152; i += 256) {
        const float4* up = (const float4*)(g_u + ((size_t)b * 1152 + i) * 8);
        float4 ua = up[0], ub = up[1];
        const float* wp = cw + ((size_t)o * 1152 + i) * 128;
        float4* xp = (float4*)(g_xhat + (((size_t)bo * 1152) + i) * 16);
        float r[16];
#pragma unroll
        for (int d = 0; d < 16; d++) {
            const float4* w4 = (const float4*)(wp + d * 8);
            float4 wa = w4[0], wb = w4[1];
            r[d] = wa.x * ua.x + wa.y * ua.y + wa.z * ua.z + wa.w * ua.w +
                   wb.x * ub.x + wb.y * ub.y + wb.z * ub.z + wb.w * ub.w;
        }
#pragma unroll
        for (int q = 0; q < 4; q++)
            xp[q] = make_float4(r[4 * q], r[4 * q + 1], r[4 * q + 2], r[4 * q + 3]);
    }
}

// ---------------- fused routing A+B ----------------
template <int MODE>
__global__ __launch_bounds__(256) void routeAB_kernel(const float* __restrict__ blin_g,
                                                      float* __restrict__ blout_g) {
    extern __shared__ float sm[];
    float* xs = sm;                 // [1152][17]
    float* cs = sm + 1152 * 17;     // [1152]
    __shared__ float sred[256];
    __shared__ float sd[16];
    __shared__ float sscale;

    int bo = blockIdx.x;
    int b = bo / 10, o = bo % 10;
    int t = threadIdx.x;

    const float4* xg = (const float4*)(g_xhat + (size_t)bo * 1152 * 16);
    for (int j = t; j < 1152 * 4; j += 256) {
        float4 v4 = xg[j];
        int i = j >> 2, q = j & 3;
        float* dst = xs + i * 17 + q * 4;
        dst[0] = v4.x; dst[1] = v4.y; dst[2] = v4.z; dst[3] = v4.w;
    }

    if (MODE == 1) {
        const float* blb = g_blog0 + (size_t)b * 10 * 1152;
        for (int i = t; i < 1152; i += 256) {
            float vals[10];
            float m = -1e30f;
#pragma unroll
            for (int oo = 0; oo < 10; oo++) {
                vals[oo] = blb[(size_t)oo * 1152 + i];
                m = fmaxf(m, vals[oo]);
            }
            float sum = 0.f;
#pragma unroll
            for (int oo = 0; oo < 10; oo++) sum += expf(vals[oo] - m);
            cs[i] = expf(vals[o] - m) / sum;
        }
    } else {
        for (int i = t; i < 1152; i += 256) cs[i] = 0.1f;
    }
    __syncthreads();

    int d = t & 15, g = t >> 4;
    float acc = 0.f;
    for (int i = g; i < 1152; i += 16)
        acc += cs[i] * xs[i * 17 + d];
    sred[t] = acc;
    __syncthreads();

    if (t < 16) {
        float s = 0.f;
#pragma unroll
        for (int gg = 0; gg < 16; gg++) s += sred[gg * 16 + t];
        sd[t] = s;
    }
    __syncthreads();

    if (t == 0) {
        float n2 = 0.f;
#pragma unroll
        for (int dd = 0; dd < 16; dd++) n2 += sd[dd] * sd[dd];
        float n = sqrtf(n2);
        sscale = n2 / (1.f + n2) / (n + 1e-8f);
    }
    __syncthreads();

    float scale = sscale;
    const float* blin = blin_g + (size_t)bo * 1152;
    float* blout = blout_g + (size_t)bo * 1152;
    for (int i = t; i < 1152; i += 256) {
        float dot = 0.f;
        const float* xr = xs + i * 17;
#pragma unroll
        for (int dd = 0; dd < 16; dd++) dot += sd[dd] * xr[dd];
        dot *= scale;
        blout[i] = (MODE == 1) ? (blin[i] + dot) : dot;
    }
}

// ---------------- final routing pass: softmax(blog1) -> capsule lengths ----------------
__global__ __launch_bounds__(256) void routeFinal_kernel(float* __restrict__ out) {
    __shared__ float cs[1152];
    __shared__ float sred[256];
    __shared__ float sd[16];

    int bo = blockIdx.x;
    int b = bo / 10, o = bo % 10;
    int t = threadIdx.x;

    const float* blb = g_blog1 + (size_t)b * 10 * 1152;
    for (int i = t; i < 1152; i += 256) {
        float vals[10];
        float m = -1e30f;
#pragma unroll
        for (int oo = 0; oo < 10; oo++) {
            vals[oo] = blb[(size_t)oo * 1152 + i];
            m = fmaxf(m, vals[oo]);
        }
        float sum = 0.f;
#pragma unroll
        for (int oo = 0; oo < 10; oo++) sum += expf(vals[oo] - m);
        cs[i] = expf(vals[o] - m) / sum;
    }
    __syncthreads();

    int d = t & 15, g = t >> 4;
    float acc = 0.f;
    const float* xb = g_xhat + (size_t)bo * 1152 * 16;
    for (int i = g; i < 1152; i += 16)
        acc += cs[i] * xb[(size_t)i * 16 + d];
    sred[t] = acc;
    __syncthreads();

    if (t < 16) {
        float s = 0.f;
#pragma unroll
        for (int gg = 0; gg < 16; gg++) s += sred[gg * 16 + t];
        sd[t] = s;
    }
    __syncthreads();

    if (t == 0) {
        float n2 = 0.f;
#pragma unroll
        for (int dd = 0; dd < 16; dd++) n2 += sd[dd] * sd[dd];
        float n = sqrtf(n2);
        float scale = n2 / (1.f + n2) / (n + 1e-8f);
        out[bo] = scale * n;
    }
}

// ---------------- launch ----------------
extern "C" void kernel_launch(void* const* d_in, const int* in_sizes, int n_in,
                              void* d_out, int out_size) {
    const float* x   = (const float*)d_in[0];
    const float* w1  = (const float*)d_in[1];
    const float* b1  = (const float*)d_in[2];
    const float* w2  = (const float*)d_in[3];
    const float* b2  = (const float*)d_in[4];
    const float* cw  = (const float*)d_in[5];
    float* out = (float*)d_out;

    const int CONV2_SMEM = 2 * BUFSZ;                  // 221184 B, double-buffered
    const int ROUTE_SMEM = (1152 * 17 + 1152) * 4;     // 82944 B
    const int W2_SMEM    = 256 * 81 * 4;               // 82944 B
    cudaFuncSetAttribute(conv2_mma, cudaFuncAttributeMaxDynamicSharedMemorySize, CONV2_SMEM);
    cudaFuncSetAttribute(convert_w2, cudaFuncAttributeMaxDynamicSharedMemorySize, W2_SMEM);
    cudaFuncSetAttribute(routeAB_kernel<0>, cudaFuncAttributeMaxDynamicSharedMemorySize, ROUTE_SMEM);
    cudaFuncSetAttribute(routeAB_kernel<1>, cudaFuncAttributeMaxDynamicSharedMemorySize, ROUTE_SMEM);

    float *blog0, *blog1;
    cudaGetSymbolAddress((void**)&blog0, g_blog0);
    cudaGetSymbolAddress((void**)&blog1, g_blog1);

    conv1_kernel<<<512, 256>>>(x, w1, b1);
    convert_w2<<<256, 256, W2_SMEM>>>(w2);
    conv2_mma<<<dim3(2, 72), 256, CONV2_SMEM>>>(b2);
    squash_kernel<<<(512 * 1152 + 255) / 256, 256>>>();
    xhat_kernel<<<5120, 256>>>(cw);

    routeAB_kernel<0><<<5120, 256, ROUTE_SMEM>>>(blog0, blog0);
    routeAB_kernel<1><<<5120, 256, ROUTE_SMEM>>>(blog0, blog1);
    routeFinal_kernel<<<5120, 256>>>(out);
}

// round 7
// speedup vs baseline: 3.9506x; 1.1278x over previous
#include <cuda_runtime.h>
#include <cuda_bf16.h>
#include <math.h>
#include <stdint.h>

// ---------------- scratch (static device globals; no runtime alloc) ----------------
__device__ __nv_bfloat16 g_h1_hi[(size_t)512 * 400 * 256];   // conv1 out hi, [b][pos][ci]
__device__ __nv_bfloat16 g_h1_lo[(size_t)512 * 400 * 256];   // conv1 out lo
__device__ __nv_bfloat16 g_w2_hi[81 * 256 * 256];            // pc_w hi, [kk][co][ci]
__device__ __nv_bfloat16 g_w2_lo[81 * 256 * 256];            // pc_w lo
__device__ float g_h2[512 * 9216];                           // conv2 out [b][co*36+s]
__device__ float g_u[512 * 9216];                            // squashed capsules [b][i][k]
__device__ float g_xhat[(size_t)512 * 10 * 1152 * 16];       // votes [b][o][i][d]
__device__ float g_blog0[512 * 10 * 1152];                   // routing logits ping
__device__ float g_blog1[512 * 10 * 1152];                   // routing logits pong
__device__ float g_c[512 * 10 * 1152];                       // softmax coefficients

// ---------------- PTX helpers (sm_80-era; compile on plain sm_103 target) ----------------
__device__ __forceinline__ uint32_t smem_u32(const void* p) {
    uint32_t a;
    asm("{ .reg .u64 t; cvta.to.shared.u64 t, %1; cvt.u32.u64 %0, t; }" : "=r"(a) : "l"(p));
    return a;
}
__device__ __forceinline__ void ldm_x4(uint32_t* r, uint32_t addr) {
    asm volatile("ldmatrix.sync.aligned.m8n8.x4.shared.b16 {%0,%1,%2,%3}, [%4];"
                 : "=r"(r[0]), "=r"(r[1]), "=r"(r[2]), "=r"(r[3]) : "r"(addr));
}
__device__ __forceinline__ void mma_bf16(float* c, const uint32_t* a, const uint32_t* b) {
    asm volatile("mma.sync.aligned.m16n8k16.row.col.f32.bf16.bf16.f32 "
                 "{%0,%1,%2,%3}, {%4,%5,%6,%7}, {%8,%9}, {%0,%1,%2,%3};"
                 : "+f"(c[0]), "+f"(c[1]), "+f"(c[2]), "+f"(c[3])
                 : "r"(a[0]), "r"(a[1]), "r"(a[2]), "r"(a[3]), "r"(b[0]), "r"(b[1]));
}
__device__ __forceinline__ void cp16(uint32_t dst, const void* src) {
    asm volatile("cp.async.cg.shared.global [%0], [%1], 16;" :: "r"(dst), "l"(src));
}
__device__ __forceinline__ void cp_commit() { asm volatile("cp.async.commit_group;" ::: "memory"); }
__device__ __forceinline__ void cp_wait0()  { asm volatile("cp.async.wait_group 0;" ::: "memory"); }

// ---------------- conv1: [512,1,28,28] -> channel-last bf16 hi/lo [512,400,256], ReLU ----------------
__global__ __launch_bounds__(256) void conv1_kernel(const float* __restrict__ x,
                                                    const float* __restrict__ w1,
                                                    const float* __restrict__ b1) {
    __shared__ float xs[784];
    int b  = blockIdx.x;
    int co = threadIdx.x;
    const float* xb = x + (size_t)b * 784;
    for (int idx = co; idx < 784; idx += 256) xs[idx] = xb[idx];
    __syncthreads();

    float bias = b1[co];
    const float* wco = w1 + co * 81;

    for (int oh = 0; oh < 20; oh++) {
        float acc[20];
#pragma unroll
        for (int ow = 0; ow < 20; ow++) acc[ow] = 0.f;

        for (int kh = 0; kh < 9; kh++) {
            float xr[28];
#pragma unroll
            for (int c = 0; c < 28; c++) xr[c] = xs[(oh + kh) * 28 + c];
#pragma unroll
            for (int kw = 0; kw < 9; kw++) {
                float w = __ldg(&wco[kh * 9 + kw]);
#pragma unroll
                for (int ow = 0; ow < 20; ow++) acc[ow] += w * xr[ow + kw];
            }
        }
        size_t base = (((size_t)b * 400) + oh * 20) * 256 + co;
#pragma unroll
        for (int ow = 0; ow < 20; ow++) {
            float v = acc[ow] + bias;
            v = v > 0.f ? v : 0.f;
            __nv_bfloat16 h = __float2bfloat16(v);
            __nv_bfloat16 l = __float2bfloat16(v - __bfloat162float(h));
            g_h1_hi[base + (size_t)ow * 256] = h;
            g_h1_lo[base + (size_t)ow * 256] = l;
        }
    }
}

// ---------------- pc_w convert (coalesced): [co][ci][k] fp32 -> [kk][co][ci] bf16 hi/lo ----------------
__global__ __launch_bounds__(256) void convert_w2(const float* __restrict__ pcw) {
    extern __shared__ float ws[];    // [ci][81]
    int co = blockIdx.x;
    int t = threadIdx.x;
    const float* src = pcw + (size_t)co * 256 * 81;
    for (int idx = t; idx < 256 * 81; idx += 256) ws[idx] = src[idx];
    __syncthreads();
    int ci = t;
    for (int k = 0; k < 81; k++) {
        float v = ws[ci * 81 + k];
        __nv_bfloat16 h = __float2bfloat16(v);
        __nv_bfloat16 l = __float2bfloat16(v - __bfloat162float(h));
        size_t o = ((size_t)k * 256 + co) * 256 + ci;
        g_w2_hi[o] = h;
        g_w2_lo[o] = l;
    }
}

// ---------------- conv2 via HMMA implicit GEMM, cp.async double-buffered ----------------
#define LDK 72
#define BUFSZ 110592
#define AHI 0
#define ALO 18432
#define BHI 36864
#define BLO 73728
#define NITER 324
__global__ __launch_bounds__(256, 1) void conv2_mma(const float* __restrict__ pcb) {
    extern __shared__ char smem[];
    uint32_t sb = smem_u32(smem);
    int tid = threadIdx.x;
    int wid = tid >> 5;
    int lane = tid & 31;
    int mtile = blockIdx.x;      // 0..1   (co block of 128)
    int ntile = blockIdx.y;      // 0..71  (pos block of 256)

    int wm = wid & 3;
    int wn = wid >> 2;

    int seg = tid & 7;
    int rbase = tid >> 3;
    uint32_t adst[4];
    uint32_t aoff[4];
#pragma unroll
    for (int j = 0; j < 4; j++) {
        int row = rbase + j * 32;
        adst[j] = (uint32_t)(row * LDK + seg * 8) * 2;
        aoff[j] = (uint32_t)((mtile * 128 + row) * 256 + seg * 8);
    }
    uint32_t bdst[8];
    size_t gb[8];
#pragma unroll
    for (int j = 0; j < 8; j++) {
        int row = rbase + j * 32;
        bdst[j] = (uint32_t)(row * LDK + seg * 8) * 2;
        int p = ntile * 256 + row;
        int b = p / 36;
        int s = p - b * 36;
        int oh = s / 6, ow = s - oh * 6;
        gb[j] = ((size_t)b * 400 + oh * 40 + ow * 2) * 256 + seg * 8;
    }

    float acc[2][16][4];
#pragma unroll
    for (int mt = 0; mt < 2; mt++)
#pragma unroll
        for (int nt = 0; nt < 16; nt++)
#pragma unroll
            for (int j = 0; j < 4; j++) acc[mt][nt][j] = 0.f;

    int rowA = lane & 15;
    int kgA  = (lane >> 4) << 3;
    int rowB = ((lane >> 4) << 3) + (lane & 7);
    int kgB  = ((lane >> 3) & 1) << 3;

#define STAGE(IT, BSEL) do {                                                        \
        int _it = (IT);                                                             \
        int _cb = (_it / 81) << 6;                                                  \
        int _kk = _it - (_it / 81) * 81;                                            \
        int _kh = _kk / 9, _kw = _kk - _kh * 9;                                     \
        uint32_t _bu = sb + (BSEL) * BUFSZ;                                         \
        size_t _abase = ((size_t)_kk * 256) * 256 + _cb;                            \
        size_t _boff = (size_t)(_kh * 20 + _kw) * 256 + _cb;                        \
        _Pragma("unroll")                                                           \
        for (int j = 0; j < 4; j++) {                                               \
            size_t _s = _abase + aoff[j];                                           \
            cp16(_bu + AHI + adst[j], (const char*)g_w2_hi + _s * 2);               \
            cp16(_bu + ALO + adst[j], (const char*)g_w2_lo + _s * 2);               \
        }                                                                           \
        _Pragma("unroll")                                                           \
        for (int j = 0; j < 8; j++) {                                               \
            size_t _s = gb[j] + _boff;                                              \
            cp16(_bu + BHI + bdst[j], (const char*)g_h1_hi + _s * 2);               \
            cp16(_bu + BLO + bdst[j], (const char*)g_h1_lo + _s * 2);               \
        }                                                                           \
    } while (0)

    STAGE(0, 0);
    cp_commit();
    cp_wait0();
    __syncthreads();

    for (int it = 0; it < NITER; it++) {
        if (it + 1 < NITER) { STAGE(it + 1, (it + 1) & 1); cp_commit(); }

        uint32_t bu = sb + (it & 1) * BUFSZ;
#pragma unroll
        for (int ks = 0; ks < 4; ks++) {
            int k0 = ks * 16;
            uint32_t ahi[2][4], alo[2][4];
#pragma unroll
            for (int mt = 0; mt < 2; mt++) {
                uint32_t arow = (uint32_t)((wm * 32 + mt * 16 + rowA) * LDK + k0 + kgA) * 2;
                ldm_x4(ahi[mt], bu + AHI + arow);
                ldm_x4(alo[mt], bu + ALO + arow);
            }
#pragma unroll
            for (int nh = 0; nh < 4; nh++) {
                uint32_t bhi[4][2], blo[4][2];
#pragma unroll
                for (int nq = 0; nq < 2; nq++) {
                    uint32_t brow = (uint32_t)((wn * 128 + nh * 32 + nq * 16 + rowB) * LDK + k0 + kgB) * 2;
                    uint32_t t4[4];
                    ldm_x4(t4, bu + BHI + brow);
                    bhi[2 * nq][0] = t4[0]; bhi[2 * nq][1] = t4[1];
                    bhi[2 * nq + 1][0] = t4[2]; bhi[2 * nq + 1][1] = t4[3];
                    ldm_x4(t4, bu + BLO + brow);
                    blo[2 * nq][0] = t4[0]; blo[2 * nq][1] = t4[1];
                    blo[2 * nq + 1][0] = t4[2]; blo[2 * nq + 1][1] = t4[3];
                }
#pragma unroll
                for (int mt = 0; mt < 2; mt++)
#pragma unroll
                    for (int nq = 0; nq < 4; nq++) {
                        int nt = nh * 4 + nq;
                        mma_bf16(acc[mt][nt], ahi[mt], bhi[nq]);
                        mma_bf16(acc[mt][nt], ahi[mt], blo[nq]);
                        mma_bf16(acc[mt][nt], alo[mt], bhi[nq]);
                    }
            }
        }
        if (it + 1 < NITER) cp_wait0();
        __syncthreads();
    }

    int r0 = lane >> 2, cp = lane & 3;
#pragma unroll
    for (int mt = 0; mt < 2; mt++) {
#pragma unroll
        for (int half = 0; half < 2; half++) {
            int m = wm * 32 + mt * 16 + r0 + half * 8;
            int co = mtile * 128 + m;
            float bias = pcb[co];
#pragma unroll
            for (int nt = 0; nt < 16; nt++) {
#pragma unroll
                for (int e = 0; e < 2; e++) {
                    int p = ntile * 256 + wn * 128 + nt * 8 + 2 * cp + e;
                    int b = p / 36;
                    int s = p - b * 36;
                    g_h2[(size_t)b * 9216 + co * 36 + s] = acc[mt][nt][half * 2 + e] + bias;
                }
            }
        }
    }
}

// ---------------- squash over 8-dim capsules: g_h2 -> g_u ----------------
__global__ void squash_kernel() {
    int idx = blockIdx.x * 256 + threadIdx.x;
    if (idx >= 512 * 1152) return;
    const float4* p = (const float4*)(g_h2 + (size_t)idx * 8);
    float4 a = p[0], c = p[1];
    float n2 = a.x * a.x + a.y * a.y + a.z * a.z + a.w * a.w +
               c.x * c.x + c.y * c.y + c.z * c.z + c.w * c.w;
    float n = sqrtf(n2);
    float scale = n2 / (1.f + n2) / (n + 1e-8f);
    float4* q = (float4*)(g_u + (size_t)idx * 8);
    a.x *= scale; a.y *= scale; a.z *= scale; a.w *= scale;
    c.x *= scale; c.y *= scale; c.z *= scale; c.w *= scale;
    q[0] = a; q[1] = c;
}

// ---------------- votes, tiled: caps_w tile resident in smem, 64 b per block ----------------
// grid (10 o, 9 ichunk, 8 bchunk); smem: ws[128 i][132] (pad->conflict-free) + us[1024]
__global__ __launch_bounds__(256) void xhat_kernel(const float* __restrict__ cw) {
    extern __shared__ float xsm[];
    float* ws = xsm;                    // 128 * 132
    float* us = xsm + 128 * 132;        // 1024

    int o  = blockIdx.x;
    int ic = blockIdx.y;
    int bc = blockIdx.z;
    int t  = threadIdx.x;

    // load caps_w tile: contiguous 16384 floats -> padded rows of 132
    const float4* src = (const float4*)(cw + ((size_t)o * 1152 + ic * 128) * 128);
    for (int j = t; j < 4096; j += 256) {
        float4 v = src[j];
        int fo = j * 4;
        int il = fo >> 7, rem = fo & 127;
        *(float4*)(ws + il * 132 + rem) = v;
    }
    __syncthreads();

    int d = t & 15;
    int tr = t >> 4;

    for (int bl = 0; bl < 64; bl++) {
        int b = bc * 64 + bl;
        // stage u slice: 1024 contiguous floats
        const float4* up = (const float4*)(g_u + ((size_t)b * 1152 + ic * 128) * 8);
        __syncthreads();
        *(float4*)(us + t * 4) = up[t];
        __syncthreads();

        float* xout = g_xhat + (((size_t)(b * 10 + o) * 1152) + ic * 128) * 16;
#pragma unroll
        for (int isub = 0; isub < 8; isub++) {
            int il = isub * 16 + tr;
            const float* wr = ws + il * 132 + d * 8;
            const float* ur = us + il * 8;
            float acc = wr[0] * ur[0] + wr[1] * ur[1] + wr[2] * ur[2] + wr[3] * ur[3]
                      + wr[4] * ur[4] + wr[5] * ur[5] + wr[6] * ur[6] + wr[7] * ur[7];
            xout[il * 16 + d] = acc;
        }
    }
}

// ---------------- softmax over output caps: c[b,o,i] = softmax_o(blog[b,o,i]) ----------------
__global__ __launch_bounds__(256) void softmax_c(const float* __restrict__ blog) {
    int idx = blockIdx.x * 256 + threadIdx.x;   // b*1152 + i
    if (idx >= 512 * 1152) return;
    int b = idx / 1152, i = idx - b * 1152;
    const float* blb = blog + (size_t)b * 10 * 1152 + i;
    float vals[10];
    float m = -1e30f;
#pragma unroll
    for (int o = 0; o < 10; o++) {
        vals[o] = blb[(size_t)o * 1152];
        m = fmaxf(m, vals[o]);
    }
    float sum = 0.f;
#pragma unroll
    for (int o = 0; o < 10; o++) { vals[o] = expf(vals[o] - m); sum += vals[o]; }
    float inv = 1.f / sum;
    float* cb = g_c + (size_t)b * 10 * 1152 + i;
#pragma unroll
    for (int o = 0; o < 10; o++) cb[(size_t)o * 1152] = vals[o] * inv;
}

// ---------------- fused routing A+B: c -> v (squash) -> logit update ----------------
// MODE 0: c = 0.1, blout = v.xhat.   MODE 1: c from g_c, blout = blin + v.xhat.
template <int MODE>
__global__ __launch_bounds__(256) void routeAB_kernel(const float* __restrict__ blin_g,
                                                      float* __restrict__ blout_g) {
    extern __shared__ float sm[];
    float* xs = sm;                 // [1152][17]
    float* cs = sm + 1152 * 17;     // [1152]
    __shared__ float sred[256];
    __shared__ float sd[16];
    __shared__ float sscale;

    int bo = blockIdx.x;
    int t = threadIdx.x;

    const float4* xg = (const float4*)(g_xhat + (size_t)bo * 1152 * 16);
    for (int j = t; j < 1152 * 4; j += 256) {
        float4 v4 = xg[j];
        int i = j >> 2, q = j & 3;
        float* dst = xs + i * 17 + q * 4;
        dst[0] = v4.x; dst[1] = v4.y; dst[2] = v4.z; dst[3] = v4.w;
    }

    if (MODE == 1) {
        const float* cg = g_c + (size_t)bo * 1152;
        for (int i = t; i < 1152; i += 256) cs[i] = cg[i];
    } else {
        for (int i = t; i < 1152; i += 256) cs[i] = 0.1f;
    }
    __syncthreads();

    int d = t & 15, g = t >> 4;
    float acc = 0.f;
    for (int i = g; i < 1152; i += 16)
        acc += cs[i] * xs[i * 17 + d];
    sred[t] = acc;
    __syncthreads();

    if (t < 16) {
        float s = 0.f;
#pragma unroll
        for (int gg = 0; gg < 16; gg++) s += sred[gg * 16 + t];
        sd[t] = s;
    }
    __syncthreads();

    if (t == 0) {
        float n2 = 0.f;
#pragma unroll
        for (int dd = 0; dd < 16; dd++) n2 += sd[dd] * sd[dd];
        float n = sqrtf(n2);
        sscale = n2 / (1.f + n2) / (n + 1e-8f);
    }
    __syncthreads();

    float scale = sscale;
    const float* blin = blin_g + (size_t)bo * 1152;
    float* blout = blout_g + (size_t)bo * 1152;
    for (int i = t; i < 1152; i += 256) {
        float dot = 0.f;
        const float* xr = xs + i * 17;
#pragma unroll
        for (int dd = 0; dd < 16; dd++) dot += sd[dd] * xr[dd];
        dot *= scale;
        blout[i] = (MODE == 1) ? (blin[i] + dot) : dot;
    }
}

// ---------------- final routing pass: c (precomputed) -> capsule lengths ----------------
__global__ __launch_bounds__(256) void routeFinal_kernel(float* __restrict__ out) {
    __shared__ float cs[1152];
    __shared__ float sred[256];
    __shared__ float sd[16];

    int bo = blockIdx.x;
    int t = threadIdx.x;

    const float* cg = g_c + (size_t)bo * 1152;
    for (int i = t; i < 1152; i += 256) cs[i] = cg[i];
    __syncthreads();

    int d = t & 15, g = t >> 4;
    float acc = 0.f;
    const float* xb = g_xhat + (size_t)bo * 1152 * 16;
    for (int i = g; i < 1152; i += 16)
        acc += cs[i] * xb[(size_t)i * 16 + d];
    sred[t] = acc;
    __syncthreads();

    if (t < 16) {
        float s = 0.f;
#pragma unroll
        for (int gg = 0; gg < 16; gg++) s += sred[gg * 16 + t];
        sd[t] = s;
    }
    __syncthreads();

    if (t == 0) {
        float n2 = 0.f;
#pragma unroll
        for (int dd = 0; dd < 16; dd++) n2 += sd[dd] * sd[dd];
        float n = sqrtf(n2);
        float scale = n2 / (1.f + n2) / (n + 1e-8f);
        out[bo] = scale * n;
    }
}

// ---------------- launch ----------------
extern "C" void kernel_launch(void* const* d_in, const int* in_sizes, int n_in,
                              void* d_out, int out_size) {
    const float* x   = (const float*)d_in[0];
    const float* w1  = (const float*)d_in[1];
    const float* b1  = (const float*)d_in[2];
    const float* w2  = (const float*)d_in[3];
    const float* b2  = (const float*)d_in[4];
    const float* cw  = (const float*)d_in[5];
    float* out = (float*)d_out;

    const int CONV2_SMEM = 2 * BUFSZ;                    // 221184 B
    const int ROUTE_SMEM = (1152 * 17 + 1152) * 4;       // 82944 B
    const int W2_SMEM    = 256 * 81 * 4;                 // 82944 B
    const int XHAT_SMEM  = (128 * 132 + 1024) * 4;       // 71680 B
    cudaFuncSetAttribute(conv2_mma, cudaFuncAttributeMaxDynamicSharedMemorySize, CONV2_SMEM);
    cudaFuncSetAttribute(convert_w2, cudaFuncAttributeMaxDynamicSharedMemorySize, W2_SMEM);
    cudaFuncSetAttribute(xhat_kernel, cudaFuncAttributeMaxDynamicSharedMemorySize, XHAT_SMEM);
    cudaFuncSetAttribute(routeAB_kernel<0>, cudaFuncAttributeMaxDynamicSharedMemorySize, ROUTE_SMEM);
    cudaFuncSetAttribute(routeAB_kernel<1>, cudaFuncAttributeMaxDynamicSharedMemorySize, ROUTE_SMEM);

    float *blog0, *blog1;
    cudaGetSymbolAddress((void**)&blog0, g_blog0);
    cudaGetSymbolAddress((void**)&blog1, g_blog1);

    conv1_kernel<<<512, 256>>>(x, w1, b1);
    convert_w2<<<256, 256, W2_SMEM>>>(w2);
    conv2_mma<<<dim3(2, 72), 256, CONV2_SMEM>>>(b2);
    squash_kernel<<<(512 * 1152 + 255) / 256, 256>>>();
    xhat_kernel<<<dim3(10, 9, 8), 256, XHAT_SMEM>>>(cw);

    routeAB_kernel<0><<<5120, 256, ROUTE_SMEM>>>(blog0, blog0);   // iter 0: uniform c
    softmax_c<<<(512 * 1152 + 255) / 256, 256>>>(blog0);
    routeAB_kernel<1><<<5120, 256, ROUTE_SMEM>>>(blog0, blog1);   // iter 1
    softmax_c<<<(512 * 1152 + 255) / 256, 256>>>(blog1);
    routeFinal_kernel<<<5120, 256>>>(out);                        // iter 2: lengths
}